// round 1
// baseline (speedup 1.0000x reference)
#include <cuda_runtime.h>
#include <cuda_bf16.h>
#include <math_constants.h>

// Problem constants
#define BATCH   4
#define SEQ     2048
#define DMODEL  2048
#define NHEADS  16
#define DHEAD   128
#define QKVDIM  (3 * DMODEL)       // 6144
#define NTOK    (BATCH * SEQ)      // 8192

// ---------------------------------------------------------------------------
// Scratch (no cudaMalloc allowed; __device__ globals are the sanctioned path)
// ---------------------------------------------------------------------------
__device__ float g_qkv[(size_t)NTOK * QKVDIM];   // [8192, 6144]
__device__ float g_y[(size_t)NTOK * DMODEL];     // [8192, 2048]

// ---------------------------------------------------------------------------
// SGEMM: C[M,N] = A[M,K] @ B[K,N] + bias[N]
// Tile 128x128, K-tile 16, 256 threads, 8x8 per-thread micro-tile.
// M % 128 == 0, N % 128 == 0, K % 16 == 0 assumed (true for all our shapes).
// ---------------------------------------------------------------------------
#define GBM 128
#define GBN 128
#define GBK 16
#define GPAD 4   // smem row padding (floats)

__global__ __launch_bounds__(256, 2)
void sgemm_bias_kernel(const float* __restrict__ A,
                       const float* __restrict__ B,
                       const float* __restrict__ bias,
                       float* __restrict__ C,
                       int M, int N, int K)
{
    __shared__ float As[GBK][GBM + GPAD];  // transposed A tile
    __shared__ float Bs[GBK][GBN + GPAD];

    const int tid = threadIdx.x;
    const int tx = tid & 15;          // 0..15 -> N direction
    const int ty = tid >> 4;          // 0..15 -> M direction

    const int m0 = blockIdx.y * GBM;
    const int n0 = blockIdx.x * GBN;

    float acc[8][8];
#pragma unroll
    for (int i = 0; i < 8; ++i)
#pragma unroll
        for (int j = 0; j < 8; ++j) acc[i][j] = 0.f;

    for (int k0 = 0; k0 < K; k0 += GBK) {
        // Load A tile: 128 rows x 16 cols = 512 float4; 2 per thread.
#pragma unroll
        for (int l = 0; l < 2; ++l) {
            int f = tid + l * 256;          // 0..511
            int row = f >> 2;               // 0..127
            int cv = f & 3;                 // 0..3  (float4 within the 16-col row)
            float4 av = *reinterpret_cast<const float4*>(
                A + (size_t)(m0 + row) * K + k0 + cv * 4);
            As[cv * 4 + 0][row] = av.x;
            As[cv * 4 + 1][row] = av.y;
            As[cv * 4 + 2][row] = av.z;
            As[cv * 4 + 3][row] = av.w;
        }
        // Load B tile: 16 rows x 128 cols = 512 float4; 2 per thread.
#pragma unroll
        for (int l = 0; l < 2; ++l) {
            int f = tid + l * 256;
            int row = f >> 5;               // 0..15
            int c4 = f & 31;                // 0..31
            float4 bv = *reinterpret_cast<const float4*>(
                B + (size_t)(k0 + row) * N + n0 + c4 * 4);
            *reinterpret_cast<float4*>(&Bs[row][c4 * 4]) = bv;
        }
        __syncthreads();

#pragma unroll
        for (int k = 0; k < GBK; ++k) {
            float4 a0 = *reinterpret_cast<const float4*>(&As[k][ty * 8]);
            float4 a1 = *reinterpret_cast<const float4*>(&As[k][ty * 8 + 4]);
            float4 b0 = *reinterpret_cast<const float4*>(&Bs[k][tx * 8]);
            float4 b1 = *reinterpret_cast<const float4*>(&Bs[k][tx * 8 + 4]);
            float ra[8] = {a0.x, a0.y, a0.z, a0.w, a1.x, a1.y, a1.z, a1.w};
            float rb[8] = {b0.x, b0.y, b0.z, b0.w, b1.x, b1.y, b1.z, b1.w};
#pragma unroll
            for (int i = 0; i < 8; ++i)
#pragma unroll
                for (int j = 0; j < 8; ++j)
                    acc[i][j] = fmaf(ra[i], rb[j], acc[i][j]);
        }
        __syncthreads();
    }

    // Epilogue with bias
#pragma unroll
    for (int i = 0; i < 8; ++i) {
        int r = m0 + ty * 8 + i;
#pragma unroll
        for (int j4 = 0; j4 < 2; ++j4) {
            float4 bv = *reinterpret_cast<const float4*>(bias + n0 + tx * 8 + j4 * 4);
            float4 v;
            v.x = acc[i][j4 * 4 + 0] + bv.x;
            v.y = acc[i][j4 * 4 + 1] + bv.y;
            v.z = acc[i][j4 * 4 + 2] + bv.z;
            v.w = acc[i][j4 * 4 + 3] + bv.w;
            *reinterpret_cast<float4*>(C + (size_t)r * N + n0 + tx * 8 + j4 * 4) = v;
        }
    }
}

// ---------------------------------------------------------------------------
// Flash attention (fp32, online softmax), causal, muP scale 1/DHEAD.
// Block: 256 threads handles one (b,h, 64-query tile). Loops over 64-key tiles.
// Writes Y in [B,T,DMODEL] layout (head h at column h*DHEAD).
// ---------------------------------------------------------------------------
#define FBM 64
#define FBN 64
#define FD  128
#define FDP (FD + 4)      // 132, padded row stride
#define FSP (FBN + 4)     // 68, padded S row stride

__global__ __launch_bounds__(256, 1)
void flash_attn_kernel(const float* __restrict__ qkv, float* __restrict__ y)
{
    extern __shared__ float sm[];
    float* Qs = sm;                         // 64 * 132
    float* Ks = Qs + FBM * FDP;             // 64 * 132
    float* Vs = Ks + FBN * FDP;             // 64 * 132
    float* Ss = Vs + FBN * FDP;             // 64 * 68
    float* m_s = Ss + FBM * FSP;            // 64
    float* l_s = m_s + FBM;                 // 64
    float* al_s = l_s + FBM;                // 64

    const int tid = threadIdx.x;
    const int tx = tid & 15;
    const int ty = tid >> 4;

    const int qtile = blockIdx.x;           // 0..31
    const int bh = blockIdx.y;              // 0..63
    const int b = bh >> 4;
    const int h = bh & 15;
    const int q0 = qtile * FBM;

    const float scale = 1.0f / (float)DHEAD;

    // Load Q tile: 64 x 128 floats = 2048 float4, 8 per thread.
#pragma unroll
    for (int l = 0; l < 8; ++l) {
        int f = tid + l * 256;
        int row = f >> 5;
        int c4 = f & 31;
        float4 v = *reinterpret_cast<const float4*>(
            qkv + (size_t)(b * SEQ + q0 + row) * QKVDIM + h * DHEAD + c4 * 4);
        *reinterpret_cast<float4*>(Qs + row * FDP + c4 * 4) = v;
    }
    if (tid < FBM) { m_s[tid] = -CUDART_INF_F; l_s[tid] = 0.f; }

    float o[4][8];
#pragma unroll
    for (int i = 0; i < 4; ++i)
#pragma unroll
        for (int j = 0; j < 8; ++j) o[i][j] = 0.f;

    __syncthreads();

    for (int kt = 0; kt <= qtile; ++kt) {
        const int k0 = kt * FBN;
        // Load K and V tiles
#pragma unroll
        for (int l = 0; l < 8; ++l) {
            int f = tid + l * 256;
            int row = f >> 5;
            int c4 = f & 31;
            size_t base = (size_t)(b * SEQ + k0 + row) * QKVDIM + h * DHEAD + c4 * 4;
            float4 kv = *reinterpret_cast<const float4*>(qkv + DMODEL + base);
            float4 vv = *reinterpret_cast<const float4*>(qkv + 2 * DMODEL + base);
            *reinterpret_cast<float4*>(Ks + row * FDP + c4 * 4) = kv;
            *reinterpret_cast<float4*>(Vs + row * FDP + c4 * 4) = vv;
        }
        __syncthreads();

        // S = Q @ K^T : each thread computes 4x4 block (rows 4*ty+i, cols 4*tx+j)
        float s[4][4];
#pragma unroll
        for (int i = 0; i < 4; ++i)
#pragma unroll
            for (int j = 0; j < 4; ++j) s[i][j] = 0.f;

        const float* qp = Qs + (4 * ty) * FDP;
        const float* kp = Ks + (4 * tx) * FDP;
#pragma unroll 8
        for (int d4 = 0; d4 < FD / 4; ++d4) {
            float4 q[4], kk[4];
#pragma unroll
            for (int i = 0; i < 4; ++i)
                q[i] = *reinterpret_cast<const float4*>(qp + i * FDP + d4 * 4);
#pragma unroll
            for (int j = 0; j < 4; ++j)
                kk[j] = *reinterpret_cast<const float4*>(kp + j * FDP + d4 * 4);
#pragma unroll
            for (int i = 0; i < 4; ++i)
#pragma unroll
                for (int j = 0; j < 4; ++j) {
                    s[i][j] = fmaf(q[i].x, kk[j].x, s[i][j]);
                    s[i][j] = fmaf(q[i].y, kk[j].y, s[i][j]);
                    s[i][j] = fmaf(q[i].z, kk[j].z, s[i][j]);
                    s[i][j] = fmaf(q[i].w, kk[j].w, s[i][j]);
                }
        }

        // scale + causal mask, store to Ss
#pragma unroll
        for (int i = 0; i < 4; ++i) {
            int qr = q0 + 4 * ty + i;
#pragma unroll
            for (int j = 0; j < 4; ++j) {
                int kc = k0 + 4 * tx + j;
                float val = s[i][j] * scale;
                if (kc > qr) val = -CUDART_INF_F;
                Ss[(4 * ty + i) * FSP + 4 * tx + j] = val;
            }
        }
        __syncthreads();

        // Online softmax: one thread per row (tid < 64)
        if (tid < FBM) {
            const int row = tid;
            float mo = m_s[row];
            float mx = mo;
#pragma unroll 8
            for (int n = 0; n < FBN; ++n)
                mx = fmaxf(mx, Ss[row * FSP + n]);
            float alpha = __expf(mo - mx);
            float sum = 0.f;
#pragma unroll 8
            for (int n = 0; n < FBN; ++n) {
                float p = __expf(Ss[row * FSP + n] - mx);
                Ss[row * FSP + n] = p;
                sum += p;
            }
            m_s[row] = mx;
            l_s[row] = alpha * l_s[row] + sum;
            al_s[row] = alpha;
        }
        __syncthreads();

        // O = alpha * O + P @ V : thread owns rows 4*ty+i, cols 8*tx+j
#pragma unroll
        for (int i = 0; i < 4; ++i) {
            float a = al_s[4 * ty + i];
#pragma unroll
            for (int j = 0; j < 8; ++j) o[i][j] *= a;
        }
#pragma unroll 4
        for (int n = 0; n < FBN; ++n) {
            float p[4];
#pragma unroll
            for (int i = 0; i < 4; ++i) p[i] = Ss[(4 * ty + i) * FSP + n];
            float4 v0 = *reinterpret_cast<const float4*>(Vs + n * FDP + 8 * tx);
            float4 v1 = *reinterpret_cast<const float4*>(Vs + n * FDP + 8 * tx + 4);
            float rv[8] = {v0.x, v0.y, v0.z, v0.w, v1.x, v1.y, v1.z, v1.w};
#pragma unroll
            for (int i = 0; i < 4; ++i)
#pragma unroll
                for (int j = 0; j < 8; ++j)
                    o[i][j] = fmaf(p[i], rv[j], o[i][j]);
        }
        __syncthreads();   // protect K/V/S smem before next iteration's loads
    }

    // Normalize and write out: y[b, q, h*128 + c]
#pragma unroll
    for (int i = 0; i < 4; ++i) {
        int r = 4 * ty + i;
        float inv = 1.0f / l_s[r];
        float4 w0, w1;
        w0.x = o[i][0] * inv; w0.y = o[i][1] * inv;
        w0.z = o[i][2] * inv; w0.w = o[i][3] * inv;
        w1.x = o[i][4] * inv; w1.y = o[i][5] * inv;
        w1.z = o[i][6] * inv; w1.w = o[i][7] * inv;
        float* dst = y + (size_t)(b * SEQ + q0 + r) * DMODEL + h * DHEAD + 8 * tx;
        *reinterpret_cast<float4*>(dst) = w0;
        *reinterpret_cast<float4*>(dst + 4) = w1;
    }
}

// ---------------------------------------------------------------------------
// Launch
// ---------------------------------------------------------------------------
extern "C" void kernel_launch(void* const* d_in, const int* in_sizes, int n_in,
                              void* d_out, int out_size)
{
    const float* x     = (const float*)d_in[0];
    const float* W_qkv = (const float*)d_in[1];
    const float* b_qkv = (const float*)d_in[2];
    const float* W_out = (const float*)d_in[3];
    const float* b_out = (const float*)d_in[4];
    float* out = (float*)d_out;

    void* p_qkv = nullptr;
    void* p_y = nullptr;
    cudaGetSymbolAddress(&p_qkv, g_qkv);
    cudaGetSymbolAddress(&p_y, g_y);
    float* qkv = (float*)p_qkv;
    float* y = (float*)p_y;

    // Flash kernel dynamic smem
    const int flash_smem = (3 * FBM * FDP + FBM * FSP + 3 * FBM) * (int)sizeof(float);
    cudaFuncSetAttribute(flash_attn_kernel,
                         cudaFuncAttributeMaxDynamicSharedMemorySize, flash_smem);

    // 1) QKV projection: [8192,2048] @ [2048,6144]
    {
        dim3 grid(QKVDIM / GBN, NTOK / GBM);
        sgemm_bias_kernel<<<grid, 256>>>(x, W_qkv, b_qkv, qkv,
                                         NTOK, QKVDIM, DMODEL);
    }
    // 2) Attention
    {
        dim3 grid(SEQ / FBM, BATCH * NHEADS);
        flash_attn_kernel<<<grid, 256, flash_smem>>>(qkv, y);
    }
    // 3) Output projection: [8192,2048] @ [2048,2048]
    {
        dim3 grid(DMODEL / GBN, NTOK / GBM);
        sgemm_bias_kernel<<<grid, 256>>>(y, W_out, b_out, out,
                                         NTOK, DMODEL, DMODEL);
    }
}

// round 3
// speedup vs baseline: 1.6567x; 1.6567x over previous
#include <cuda_runtime.h>
#include <cuda_bf16.h>
#include <math_constants.h>
#include <cstdint>

// Problem constants
#define BATCH   4
#define SEQ     2048
#define DMODEL  2048
#define NHEADS  16
#define DHEAD   128
#define QKVDIM  (3 * DMODEL)       // 6144
#define NTOK    (BATCH * SEQ)      // 8192

// ---------------------------------------------------------------------------
// Scratch (__device__ globals; no cudaMalloc allowed)
// ---------------------------------------------------------------------------
__device__ float g_qkv[(size_t)NTOK * QKVDIM];            // [8192, 6144] fp32
__device__ float g_y[(size_t)NTOK * DMODEL];              // [8192, 2048] fp32
__device__ __nv_bfloat16 g_x_hi[(size_t)NTOK * DMODEL];
__device__ __nv_bfloat16 g_x_lo[(size_t)NTOK * DMODEL];
__device__ __nv_bfloat16 g_wqkv_hi[(size_t)QKVDIM * DMODEL];  // transposed [N,K]
__device__ __nv_bfloat16 g_wqkv_lo[(size_t)QKVDIM * DMODEL];
__device__ __nv_bfloat16 g_wout_hi[(size_t)DMODEL * DMODEL];  // transposed [N,K]
__device__ __nv_bfloat16 g_wout_lo[(size_t)DMODEL * DMODEL];
__device__ __nv_bfloat16 g_y_hi[(size_t)NTOK * DMODEL];
__device__ __nv_bfloat16 g_y_lo[(size_t)NTOK * DMODEL];

// ---------------------------------------------------------------------------
// Warp-MMA helpers (plain PTX, works on compute_103 without 'a' features)
// ---------------------------------------------------------------------------
__device__ __forceinline__ uint32_t smem_u32(const void* p) {
    uint32_t a;
    asm("{ .reg .u64 t; cvta.to.shared.u64 t, %1; cvt.u32.u64 %0, t; }"
        : "=r"(a) : "l"(p));
    return a;
}

__device__ __forceinline__ void ldsm4(uint32_t r[4], uint32_t addr) {
    asm volatile("ldmatrix.sync.aligned.m8n8.x4.shared.b16 {%0,%1,%2,%3}, [%4];"
                 : "=r"(r[0]), "=r"(r[1]), "=r"(r[2]), "=r"(r[3]) : "r"(addr));
}

__device__ __forceinline__ void mma16816(float c[4], const uint32_t a[4],
                                         uint32_t b0, uint32_t b1) {
    asm volatile(
        "mma.sync.aligned.m16n8k16.row.col.f32.bf16.bf16.f32 "
        "{%0,%1,%2,%3}, {%4,%5,%6,%7}, {%8,%9}, {%0,%1,%2,%3};"
        : "+f"(c[0]), "+f"(c[1]), "+f"(c[2]), "+f"(c[3])
        : "r"(a[0]), "r"(a[1]), "r"(a[2]), "r"(a[3]), "r"(b0), "r"(b1));
}

// ---------------------------------------------------------------------------
// Split kernels: fp32 -> (hi bf16, lo bf16) with lo = bf16(v - f32(hi))
// ---------------------------------------------------------------------------
__global__ void split_kernel(const float* __restrict__ in,
                             __nv_bfloat16* __restrict__ hi,
                             __nv_bfloat16* __restrict__ lo, int n4)
{
    int i = blockIdx.x * blockDim.x + threadIdx.x;
    if (i >= n4) return;
    float4 v = reinterpret_cast<const float4*>(in)[i];
    float vv[4] = {v.x, v.y, v.z, v.w};
    unsigned short hraw[4], lraw[4];
#pragma unroll
    for (int j = 0; j < 4; ++j) {
        __nv_bfloat16 h = __float2bfloat16(vv[j]);
        __nv_bfloat16 l = __float2bfloat16(vv[j] - __bfloat162float(h));
        hraw[j] = __bfloat16_as_ushort(h);
        lraw[j] = __bfloat16_as_ushort(l);
    }
    reinterpret_cast<uint64_t*>(hi)[i] = *reinterpret_cast<uint64_t*>(hraw);
    reinterpret_cast<uint64_t*>(lo)[i] = *reinterpret_cast<uint64_t*>(lraw);
}

// W [K,N] fp32 -> Thi/Tlo [N,K] bf16 (transpose + split)
__global__ void transpose_split_kernel(const float* __restrict__ W,
                                       __nv_bfloat16* __restrict__ Thi,
                                       __nv_bfloat16* __restrict__ Tlo,
                                       int K, int N)
{
    __shared__ float tile[32][33];
    int nx = blockIdx.x * 32 + threadIdx.x;   // N index (read)
    int k0 = blockIdx.y * 32;
#pragma unroll
    for (int j = 0; j < 32; j += 8)
        tile[threadIdx.y + j][threadIdx.x] = W[(size_t)(k0 + threadIdx.y + j) * N + nx];
    __syncthreads();
    int k = k0 + threadIdx.x;                 // K index (write, contiguous)
    int nbase = blockIdx.x * 32 + threadIdx.y;
#pragma unroll
    for (int j = 0; j < 32; j += 8) {
        float v = tile[threadIdx.x][threadIdx.y + j];
        __nv_bfloat16 h = __float2bfloat16(v);
        Thi[(size_t)(nbase + j) * K + k] = h;
        Tlo[(size_t)(nbase + j) * K + k] = __float2bfloat16(v - __bfloat162float(h));
    }
}

// ---------------------------------------------------------------------------
// bf16x3 GEMM via warp mma.sync: C[M,N] = A[M,K] @ Bt[N,K]^T + bias
// CTA tile 128x128, 8 warps (2 M x 4 N), warp tile 64x32, K-chunk 64.
// ---------------------------------------------------------------------------
#define TBM 128
#define TBN 128
#define TKC 64
#define STRB 144            // smem row stride in bytes (64 bf16 + 8 pad)
#define SA_HI 0
#define SA_LO 18432
#define SB_HI 36864
#define SB_LO 55296
#define GSMEM 73728

__global__ __launch_bounds__(256, 2)
void gemm_mma_kernel(const __nv_bfloat16* __restrict__ Ahi,
                     const __nv_bfloat16* __restrict__ Alo,
                     const __nv_bfloat16* __restrict__ Bhi,
                     const __nv_bfloat16* __restrict__ Blo,
                     const float* __restrict__ bias,
                     float* __restrict__ C,
                     int M, int N, int K)
{
    extern __shared__ char sm[];
    const uint32_t sbase = smem_u32(sm);
    const int tid = threadIdx.x;
    const int wid = tid >> 5;
    const int lane = tid & 31;
    const int m0 = blockIdx.y * TBM;
    const int n0 = blockIdx.x * TBN;
    const int wm = wid & 1;          // 2 warps in M (64 rows each)
    const int wn = wid >> 1;         // 4 warps in N (32 cols each)

    float acc[4][4][4];
#pragma unroll
    for (int i = 0; i < 4; ++i)
#pragma unroll
        for (int j = 0; j < 4; ++j)
#pragma unroll
            for (int k = 0; k < 4; ++k) acc[i][j][k] = 0.f;

    // ldmatrix per-lane address components
    const int lrow = lane & 15;                       // A: row within 16
    const int lkb  = (lane & 16) ? 16 : 0;            // A: +8 bf16 in k
    const int bn   = ((lane & 16) ? 8 : 0) + (lane & 7);  // B: n within 16
    const int bkb  = (lane & 8) ? 16 : 0;             // B: +8 bf16 in k

    const uint32_t aHiB = sbase + SA_HI + (wm * 64 + lrow) * STRB + lkb;
    const uint32_t aLoB = aHiB + (SA_LO - SA_HI);
    const uint32_t bHiB = sbase + SB_HI + (wn * 32 + bn) * STRB + bkb;
    const uint32_t bLoB = bHiB + (SB_LO - SB_HI);

    const int nchunk = K / TKC;
    for (int c = 0; c < nchunk; ++c) {
        const int k0 = c * TKC;
        // Load 4 tiles of 128 rows x 64 bf16 (128B/row), 4 x uint4 per thread each
#pragma unroll
        for (int l = 0; l < 4; ++l) {
            int f = tid + l * 256;               // 0..1023
            int row = f >> 3;
            int c16 = f & 7;
            uint32_t so = row * STRB + c16 * 16;
            size_t ga = (size_t)(m0 + row) * K + k0 + c16 * 8;
            size_t gb = (size_t)(n0 + row) * K + k0 + c16 * 8;
            *reinterpret_cast<uint4*>(sm + SA_HI + so) =
                *reinterpret_cast<const uint4*>(Ahi + ga);
            *reinterpret_cast<uint4*>(sm + SA_LO + so) =
                *reinterpret_cast<const uint4*>(Alo + ga);
            *reinterpret_cast<uint4*>(sm + SB_HI + so) =
                *reinterpret_cast<const uint4*>(Bhi + gb);
            *reinterpret_cast<uint4*>(sm + SB_LO + so) =
                *reinterpret_cast<const uint4*>(Blo + gb);
        }
        __syncthreads();

#pragma unroll
        for (int ks = 0; ks < 4; ++ks) {
            uint32_t a[4][4], bh[2][4], bl[2][4];
#pragma unroll
            for (int mt = 0; mt < 4; ++mt)
                ldsm4(a[mt], aHiB + mt * (16 * STRB) + ks * 32);
#pragma unroll
            for (int np = 0; np < 2; ++np) {
                ldsm4(bh[np], bHiB + np * (16 * STRB) + ks * 32);
                ldsm4(bl[np], bLoB + np * (16 * STRB) + ks * 32);
            }
            // Ahi * Bhi
#pragma unroll
            for (int mt = 0; mt < 4; ++mt)
#pragma unroll
                for (int nt = 0; nt < 4; ++nt)
                    mma16816(acc[mt][nt], a[mt],
                             bh[nt >> 1][(nt & 1) * 2], bh[nt >> 1][(nt & 1) * 2 + 1]);
            // Ahi * Blo
#pragma unroll
            for (int mt = 0; mt < 4; ++mt)
#pragma unroll
                for (int nt = 0; nt < 4; ++nt)
                    mma16816(acc[mt][nt], a[mt],
                             bl[nt >> 1][(nt & 1) * 2], bl[nt >> 1][(nt & 1) * 2 + 1]);
            // Alo * Bhi (overwrite A frags)
#pragma unroll
            for (int mt = 0; mt < 4; ++mt)
                ldsm4(a[mt], aLoB + mt * (16 * STRB) + ks * 32);
#pragma unroll
            for (int mt = 0; mt < 4; ++mt)
#pragma unroll
                for (int nt = 0; nt < 4; ++nt)
                    mma16816(acc[mt][nt], a[mt],
                             bh[nt >> 1][(nt & 1) * 2], bh[nt >> 1][(nt & 1) * 2 + 1]);
        }
        __syncthreads();
    }

    // Epilogue: C[m][n] = acc + bias[n]
    const int rbase = m0 + wm * 64 + (lane >> 2);
    const int cbase = n0 + wn * 32 + (lane & 3) * 2;
#pragma unroll
    for (int mt = 0; mt < 4; ++mt) {
#pragma unroll
        for (int nt = 0; nt < 4; ++nt) {
            int r = rbase + mt * 16;
            int col = cbase + nt * 8;
            float2 bv = *reinterpret_cast<const float2*>(bias + col);
            float2 v0, v1;
            v0.x = acc[mt][nt][0] + bv.x;
            v0.y = acc[mt][nt][1] + bv.y;
            v1.x = acc[mt][nt][2] + bv.x;
            v1.y = acc[mt][nt][3] + bv.y;
            *reinterpret_cast<float2*>(C + (size_t)r * N + col) = v0;
            *reinterpret_cast<float2*>(C + (size_t)(r + 8) * N + col) = v1;
        }
    }
}

// ---------------------------------------------------------------------------
// Flash attention (fp32, online softmax), causal, muP scale 1/DHEAD (unchanged)
// ---------------------------------------------------------------------------
#define FBM 64
#define FBN 64
#define FD  128
#define FDP (FD + 4)
#define FSP (FBN + 4)

__global__ __launch_bounds__(256, 1)
void flash_attn_kernel(const float* __restrict__ qkv, float* __restrict__ y)
{
    extern __shared__ float smf[];
    float* Qs = smf;
    float* Ks = Qs + FBM * FDP;
    float* Vs = Ks + FBN * FDP;
    float* Ss = Vs + FBN * FDP;
    float* m_s = Ss + FBM * FSP;
    float* l_s = m_s + FBM;
    float* al_s = l_s + FBM;

    const int tid = threadIdx.x;
    const int tx = tid & 15;
    const int ty = tid >> 4;

    const int qtile = blockIdx.x;
    const int bh = blockIdx.y;
    const int b = bh >> 4;
    const int h = bh & 15;
    const int q0 = qtile * FBM;

    const float scale = 1.0f / (float)DHEAD;

#pragma unroll
    for (int l = 0; l < 8; ++l) {
        int f = tid + l * 256;
        int row = f >> 5;
        int c4 = f & 31;
        float4 v = *reinterpret_cast<const float4*>(
            qkv + (size_t)(b * SEQ + q0 + row) * QKVDIM + h * DHEAD + c4 * 4);
        *reinterpret_cast<float4*>(Qs + row * FDP + c4 * 4) = v;
    }
    if (tid < FBM) { m_s[tid] = -CUDART_INF_F; l_s[tid] = 0.f; }

    float o[4][8];
#pragma unroll
    for (int i = 0; i < 4; ++i)
#pragma unroll
        for (int j = 0; j < 8; ++j) o[i][j] = 0.f;

    __syncthreads();

    for (int kt = 0; kt <= qtile; ++kt) {
        const int k0 = kt * FBN;
#pragma unroll
        for (int l = 0; l < 8; ++l) {
            int f = tid + l * 256;
            int row = f >> 5;
            int c4 = f & 31;
            size_t base = (size_t)(b * SEQ + k0 + row) * QKVDIM + h * DHEAD + c4 * 4;
            float4 kv = *reinterpret_cast<const float4*>(qkv + DMODEL + base);
            float4 vv = *reinterpret_cast<const float4*>(qkv + 2 * DMODEL + base);
            *reinterpret_cast<float4*>(Ks + row * FDP + c4 * 4) = kv;
            *reinterpret_cast<float4*>(Vs + row * FDP + c4 * 4) = vv;
        }
        __syncthreads();

        float s[4][4];
#pragma unroll
        for (int i = 0; i < 4; ++i)
#pragma unroll
            for (int j = 0; j < 4; ++j) s[i][j] = 0.f;

        const float* qp = Qs + (4 * ty) * FDP;
        const float* kp = Ks + (4 * tx) * FDP;
#pragma unroll 8
        for (int d4 = 0; d4 < FD / 4; ++d4) {
            float4 q[4], kk[4];
#pragma unroll
            for (int i = 0; i < 4; ++i)
                q[i] = *reinterpret_cast<const float4*>(qp + i * FDP + d4 * 4);
#pragma unroll
            for (int j = 0; j < 4; ++j)
                kk[j] = *reinterpret_cast<const float4*>(kp + j * FDP + d4 * 4);
#pragma unroll
            for (int i = 0; i < 4; ++i)
#pragma unroll
                for (int j = 0; j < 4; ++j) {
                    s[i][j] = fmaf(q[i].x, kk[j].x, s[i][j]);
                    s[i][j] = fmaf(q[i].y, kk[j].y, s[i][j]);
                    s[i][j] = fmaf(q[i].z, kk[j].z, s[i][j]);
                    s[i][j] = fmaf(q[i].w, kk[j].w, s[i][j]);
                }
        }

#pragma unroll
        for (int i = 0; i < 4; ++i) {
            int qr = q0 + 4 * ty + i;
#pragma unroll
            for (int j = 0; j < 4; ++j) {
                int kc = k0 + 4 * tx + j;
                float val = s[i][j] * scale;
                if (kc > qr) val = -CUDART_INF_F;
                Ss[(4 * ty + i) * FSP + 4 * tx + j] = val;
            }
        }
        __syncthreads();

        if (tid < FBM) {
            const int row = tid;
            float mo = m_s[row];
            float mx = mo;
#pragma unroll 8
            for (int n = 0; n < FBN; ++n)
                mx = fmaxf(mx, Ss[row * FSP + n]);
            float alpha = __expf(mo - mx);
            float sum = 0.f;
#pragma unroll 8
            for (int n = 0; n < FBN; ++n) {
                float p = __expf(Ss[row * FSP + n] - mx);
                Ss[row * FSP + n] = p;
                sum += p;
            }
            m_s[row] = mx;
            l_s[row] = alpha * l_s[row] + sum;
            al_s[row] = alpha;
        }
        __syncthreads();

#pragma unroll
        for (int i = 0; i < 4; ++i) {
            float a = al_s[4 * ty + i];
#pragma unroll
            for (int j = 0; j < 8; ++j) o[i][j] *= a;
        }
#pragma unroll 4
        for (int n = 0; n < FBN; ++n) {
            float p[4];
#pragma unroll
            for (int i = 0; i < 4; ++i) p[i] = Ss[(4 * ty + i) * FSP + n];
            float4 v0 = *reinterpret_cast<const float4*>(Vs + n * FDP + 8 * tx);
            float4 v1 = *reinterpret_cast<const float4*>(Vs + n * FDP + 8 * tx + 4);
            float rv[8] = {v0.x, v0.y, v0.z, v0.w, v1.x, v1.y, v1.z, v1.w};
#pragma unroll
            for (int i = 0; i < 4; ++i)
#pragma unroll
                for (int j = 0; j < 8; ++j)
                    o[i][j] = fmaf(p[i], rv[j], o[i][j]);
        }
        __syncthreads();
    }

#pragma unroll
    for (int i = 0; i < 4; ++i) {
        int r = 4 * ty + i;
        float inv = 1.0f / l_s[r];
        float4 w0, w1;
        w0.x = o[i][0] * inv; w0.y = o[i][1] * inv;
        w0.z = o[i][2] * inv; w0.w = o[i][3] * inv;
        w1.x = o[i][4] * inv; w1.y = o[i][5] * inv;
        w1.z = o[i][6] * inv; w1.w = o[i][7] * inv;
        float* dst = y + (size_t)(b * SEQ + q0 + r) * DMODEL + h * DHEAD + 8 * tx;
        *reinterpret_cast<float4*>(dst) = w0;
        *reinterpret_cast<float4*>(dst + 4) = w1;
    }
}

// ---------------------------------------------------------------------------
// Launch
// ---------------------------------------------------------------------------
extern "C" void kernel_launch(void* const* d_in, const int* in_sizes, int n_in,
                              void* d_out, int out_size)
{
    const float* x     = (const float*)d_in[0];
    const float* W_qkv = (const float*)d_in[1];
    const float* b_qkv = (const float*)d_in[2];
    const float* W_out = (const float*)d_in[3];
    const float* b_out = (const float*)d_in[4];
    float* out = (float*)d_out;

    void *p_qkv, *p_y, *p_xh, *p_xl, *p_wqh, *p_wql, *p_woh, *p_wol, *p_yh, *p_yl;
    cudaGetSymbolAddress(&p_qkv, g_qkv);
    cudaGetSymbolAddress(&p_y, g_y);
    cudaGetSymbolAddress(&p_xh, g_x_hi);
    cudaGetSymbolAddress(&p_xl, g_x_lo);
    cudaGetSymbolAddress(&p_wqh, g_wqkv_hi);
    cudaGetSymbolAddress(&p_wql, g_wqkv_lo);
    cudaGetSymbolAddress(&p_woh, g_wout_hi);
    cudaGetSymbolAddress(&p_wol, g_wout_lo);
    cudaGetSymbolAddress(&p_yh, g_y_hi);
    cudaGetSymbolAddress(&p_yl, g_y_lo);

    float* qkv = (float*)p_qkv;
    float* y = (float*)p_y;

    cudaFuncSetAttribute(gemm_mma_kernel,
                         cudaFuncAttributeMaxDynamicSharedMemorySize, GSMEM);
    const int flash_smem = (3 * FBM * FDP + FBM * FSP + 3 * FBM) * (int)sizeof(float);
    cudaFuncSetAttribute(flash_attn_kernel,
                         cudaFuncAttributeMaxDynamicSharedMemorySize, flash_smem);

    // 0) Splits
    {
        int n4 = NTOK * DMODEL / 4;
        split_kernel<<<(n4 + 255) / 256, 256>>>(x, (__nv_bfloat16*)p_xh,
                                                (__nv_bfloat16*)p_xl, n4);
        dim3 blk(32, 8);
        transpose_split_kernel<<<dim3(QKVDIM / 32, DMODEL / 32), blk>>>(
            W_qkv, (__nv_bfloat16*)p_wqh, (__nv_bfloat16*)p_wql, DMODEL, QKVDIM);
        transpose_split_kernel<<<dim3(DMODEL / 32, DMODEL / 32), blk>>>(
            W_out, (__nv_bfloat16*)p_woh, (__nv_bfloat16*)p_wol, DMODEL, DMODEL);
    }

    // 1) QKV projection: [8192,2048] @ [2048,6144]^T-stored (mma.sync bf16x3)
    gemm_mma_kernel<<<dim3(QKVDIM / TBN, NTOK / TBM), 256, GSMEM>>>(
        (const __nv_bfloat16*)p_xh, (const __nv_bfloat16*)p_xl,
        (const __nv_bfloat16*)p_wqh, (const __nv_bfloat16*)p_wql,
        b_qkv, qkv, NTOK, QKVDIM, DMODEL);

    // 2) Attention
    flash_attn_kernel<<<dim3(SEQ / FBM, BATCH * NHEADS), 256, flash_smem>>>(qkv, y);

    // 3) Split y, then output projection
    {
        int n4 = NTOK * DMODEL / 4;
        split_kernel<<<(n4 + 255) / 256, 256>>>(y, (__nv_bfloat16*)p_yh,
                                                (__nv_bfloat16*)p_yl, n4);
    }
    gemm_mma_kernel<<<dim3(DMODEL / TBN, NTOK / TBM), 256, GSMEM>>>(
        (const __nv_bfloat16*)p_yh, (const __nv_bfloat16*)p_yl,
        (const __nv_bfloat16*)p_woh, (const __nv_bfloat16*)p_wol,
        b_out, out, NTOK, DMODEL, DMODEL);
}

// round 4
// speedup vs baseline: 3.5995x; 2.1727x over previous
#include <cuda_runtime.h>
#include <cuda_bf16.h>
#include <math_constants.h>
#include <cstdint>

// Problem constants
#define BATCH   4
#define SEQ     2048
#define DMODEL  2048
#define NHEADS  16
#define DHEAD   128
#define QKVDIM  (3 * DMODEL)       // 6144
#define NTOK    (BATCH * SEQ)      // 8192

// ---------------------------------------------------------------------------
// Scratch (__device__ globals; no cudaMalloc allowed)
// ---------------------------------------------------------------------------
__device__ __nv_bfloat16 g_x_hi[(size_t)NTOK * DMODEL];
__device__ __nv_bfloat16 g_x_lo[(size_t)NTOK * DMODEL];
__device__ __nv_bfloat16 g_wqkv_hi[(size_t)QKVDIM * DMODEL];  // transposed [N,K]
__device__ __nv_bfloat16 g_wqkv_lo[(size_t)QKVDIM * DMODEL];
__device__ __nv_bfloat16 g_wout_hi[(size_t)DMODEL * DMODEL];  // transposed [N,K]
__device__ __nv_bfloat16 g_wout_lo[(size_t)DMODEL * DMODEL];
__device__ __nv_bfloat16 g_qkv_hi[(size_t)NTOK * QKVDIM];
__device__ __nv_bfloat16 g_qkv_lo[(size_t)NTOK * QKVDIM];
__device__ __nv_bfloat16 g_y_hi[(size_t)NTOK * DMODEL];
__device__ __nv_bfloat16 g_y_lo[(size_t)NTOK * DMODEL];

// ---------------------------------------------------------------------------
// Warp-MMA helpers (plain PTX, compute_103-safe)
// ---------------------------------------------------------------------------
__device__ __forceinline__ uint32_t smem_u32(const void* p) {
    uint32_t a;
    asm("{ .reg .u64 t; cvta.to.shared.u64 t, %1; cvt.u32.u64 %0, t; }"
        : "=r"(a) : "l"(p));
    return a;
}

__device__ __forceinline__ void ldsm4(uint32_t r[4], uint32_t addr) {
    asm volatile("ldmatrix.sync.aligned.m8n8.x4.shared.b16 {%0,%1,%2,%3}, [%4];"
                 : "=r"(r[0]), "=r"(r[1]), "=r"(r[2]), "=r"(r[3]) : "r"(addr));
}
__device__ __forceinline__ void ldsm4t(uint32_t r[4], uint32_t addr) {
    asm volatile("ldmatrix.sync.aligned.m8n8.x4.trans.shared.b16 {%0,%1,%2,%3}, [%4];"
                 : "=r"(r[0]), "=r"(r[1]), "=r"(r[2]), "=r"(r[3]) : "r"(addr));
}

__device__ __forceinline__ void mma16816(float c[4], const uint32_t a[4],
                                         uint32_t b0, uint32_t b1) {
    asm volatile(
        "mma.sync.aligned.m16n8k16.row.col.f32.bf16.bf16.f32 "
        "{%0,%1,%2,%3}, {%4,%5,%6,%7}, {%8,%9}, {%0,%1,%2,%3};"
        : "+f"(c[0]), "+f"(c[1]), "+f"(c[2]), "+f"(c[3])
        : "r"(a[0]), "r"(a[1]), "r"(a[2]), "r"(a[3]), "r"(b0), "r"(b1));
}

// pack two fp32 -> bf16x2 (lo in bits [0,16), hi in [16,32))
__device__ __forceinline__ uint32_t pack_bf16x2(float lo, float hi) {
    uint32_t r;
    asm("cvt.rn.bf16x2.f32 %0, %1, %2;" : "=r"(r) : "f"(hi), "f"(lo));
    return r;
}

// ---------------------------------------------------------------------------
// Split kernels: fp32 -> (hi bf16, lo bf16) with lo = bf16(v - f32(hi))
// ---------------------------------------------------------------------------
__global__ void split_kernel(const float* __restrict__ in,
                             __nv_bfloat16* __restrict__ hi,
                             __nv_bfloat16* __restrict__ lo, int n4)
{
    int i = blockIdx.x * blockDim.x + threadIdx.x;
    if (i >= n4) return;
    float4 v = reinterpret_cast<const float4*>(in)[i];
    float vv[4] = {v.x, v.y, v.z, v.w};
    unsigned short hraw[4], lraw[4];
#pragma unroll
    for (int j = 0; j < 4; ++j) {
        __nv_bfloat16 h = __float2bfloat16(vv[j]);
        __nv_bfloat16 l = __float2bfloat16(vv[j] - __bfloat162float(h));
        hraw[j] = __bfloat16_as_ushort(h);
        lraw[j] = __bfloat16_as_ushort(l);
    }
    reinterpret_cast<uint64_t*>(hi)[i] = *reinterpret_cast<uint64_t*>(hraw);
    reinterpret_cast<uint64_t*>(lo)[i] = *reinterpret_cast<uint64_t*>(lraw);
}

// W [K,N] fp32 -> Thi/Tlo [N,K] bf16 (transpose + split)
__global__ void transpose_split_kernel(const float* __restrict__ W,
                                       __nv_bfloat16* __restrict__ Thi,
                                       __nv_bfloat16* __restrict__ Tlo,
                                       int K, int N)
{
    __shared__ float tile[32][33];
    int nx = blockIdx.x * 32 + threadIdx.x;
    int k0 = blockIdx.y * 32;
#pragma unroll
    for (int j = 0; j < 32; j += 8)
        tile[threadIdx.y + j][threadIdx.x] = W[(size_t)(k0 + threadIdx.y + j) * N + nx];
    __syncthreads();
    int k = k0 + threadIdx.x;
    int nbase = blockIdx.x * 32 + threadIdx.y;
#pragma unroll
    for (int j = 0; j < 32; j += 8) {
        float v = tile[threadIdx.x][threadIdx.y + j];
        __nv_bfloat16 h = __float2bfloat16(v);
        Thi[(size_t)(nbase + j) * K + k] = h;
        Tlo[(size_t)(nbase + j) * K + k] = __float2bfloat16(v - __bfloat162float(h));
    }
}

// ---------------------------------------------------------------------------
// bf16x3 GEMM via warp mma.sync: C[M,N] = A[M,K] @ Bt[N,K]^T + bias
// CTA tile 128x128, 8 warps (2 M x 4 N), warp tile 64x32, K-chunk 64.
// Epilogue: fp32 write (Cf) OR bf16 hi/lo split write (Chi/Clo).
// ---------------------------------------------------------------------------
#define TBM 128
#define TBN 128
#define TKC 64
#define STRB 144            // smem row stride in bytes (64 bf16 + 8 pad)
#define SA_HI 0
#define SA_LO 18432
#define SB_HI 36864
#define SB_LO 55296
#define GSMEM 73728

__global__ __launch_bounds__(256, 2)
void gemm_mma_kernel(const __nv_bfloat16* __restrict__ Ahi,
                     const __nv_bfloat16* __restrict__ Alo,
                     const __nv_bfloat16* __restrict__ Bhi,
                     const __nv_bfloat16* __restrict__ Blo,
                     const float* __restrict__ bias,
                     float* __restrict__ Cf,
                     __nv_bfloat16* __restrict__ Chi,
                     __nv_bfloat16* __restrict__ Clo,
                     int M, int N, int K)
{
    extern __shared__ char sm[];
    const uint32_t sbase = smem_u32(sm);
    const int tid = threadIdx.x;
    const int wid = tid >> 5;
    const int lane = tid & 31;
    const int m0 = blockIdx.y * TBM;
    const int n0 = blockIdx.x * TBN;
    const int wm = wid & 1;
    const int wn = wid >> 1;

    float acc[4][4][4];
#pragma unroll
    for (int i = 0; i < 4; ++i)
#pragma unroll
        for (int j = 0; j < 4; ++j)
#pragma unroll
            for (int k = 0; k < 4; ++k) acc[i][j][k] = 0.f;

    const int lrow = lane & 15;
    const int lkb  = (lane & 16) ? 16 : 0;
    const int bn   = ((lane & 16) ? 8 : 0) + (lane & 7);
    const int bkb  = (lane & 8) ? 16 : 0;

    const uint32_t aHiB = sbase + SA_HI + (wm * 64 + lrow) * STRB + lkb;
    const uint32_t aLoB = aHiB + (SA_LO - SA_HI);
    const uint32_t bHiB = sbase + SB_HI + (wn * 32 + bn) * STRB + bkb;
    const uint32_t bLoB = bHiB + (SB_LO - SB_HI);

    const int nchunk = K / TKC;
    for (int c = 0; c < nchunk; ++c) {
        const int k0 = c * TKC;
#pragma unroll
        for (int l = 0; l < 4; ++l) {
            int f = tid + l * 256;
            int row = f >> 3;
            int c16 = f & 7;
            uint32_t so = row * STRB + c16 * 16;
            size_t ga = (size_t)(m0 + row) * K + k0 + c16 * 8;
            size_t gb = (size_t)(n0 + row) * K + k0 + c16 * 8;
            *reinterpret_cast<uint4*>(sm + SA_HI + so) =
                *reinterpret_cast<const uint4*>(Ahi + ga);
            *reinterpret_cast<uint4*>(sm + SA_LO + so) =
                *reinterpret_cast<const uint4*>(Alo + ga);
            *reinterpret_cast<uint4*>(sm + SB_HI + so) =
                *reinterpret_cast<const uint4*>(Bhi + gb);
            *reinterpret_cast<uint4*>(sm + SB_LO + so) =
                *reinterpret_cast<const uint4*>(Blo + gb);
        }
        __syncthreads();

#pragma unroll
        for (int ks = 0; ks < 4; ++ks) {
            uint32_t a[4][4], bh[2][4], bl[2][4];
#pragma unroll
            for (int mt = 0; mt < 4; ++mt)
                ldsm4(a[mt], aHiB + mt * (16 * STRB) + ks * 32);
#pragma unroll
            for (int np = 0; np < 2; ++np) {
                ldsm4(bh[np], bHiB + np * (16 * STRB) + ks * 32);
                ldsm4(bl[np], bLoB + np * (16 * STRB) + ks * 32);
            }
#pragma unroll
            for (int mt = 0; mt < 4; ++mt)
#pragma unroll
                for (int nt = 0; nt < 4; ++nt)
                    mma16816(acc[mt][nt], a[mt],
                             bh[nt >> 1][(nt & 1) * 2], bh[nt >> 1][(nt & 1) * 2 + 1]);
#pragma unroll
            for (int mt = 0; mt < 4; ++mt)
#pragma unroll
                for (int nt = 0; nt < 4; ++nt)
                    mma16816(acc[mt][nt], a[mt],
                             bl[nt >> 1][(nt & 1) * 2], bl[nt >> 1][(nt & 1) * 2 + 1]);
#pragma unroll
            for (int mt = 0; mt < 4; ++mt)
                ldsm4(a[mt], aLoB + mt * (16 * STRB) + ks * 32);
#pragma unroll
            for (int mt = 0; mt < 4; ++mt)
#pragma unroll
                for (int nt = 0; nt < 4; ++nt)
                    mma16816(acc[mt][nt], a[mt],
                             bh[nt >> 1][(nt & 1) * 2], bh[nt >> 1][(nt & 1) * 2 + 1]);
        }
        __syncthreads();
    }

    // Epilogue
    const int rbase = m0 + wm * 64 + (lane >> 2);
    const int cbase = n0 + wn * 32 + (lane & 3) * 2;
    if (Cf) {
#pragma unroll
        for (int mt = 0; mt < 4; ++mt) {
#pragma unroll
            for (int nt = 0; nt < 4; ++nt) {
                int r = rbase + mt * 16;
                int col = cbase + nt * 8;
                float2 bv = *reinterpret_cast<const float2*>(bias + col);
                float2 v0, v1;
                v0.x = acc[mt][nt][0] + bv.x;
                v0.y = acc[mt][nt][1] + bv.y;
                v1.x = acc[mt][nt][2] + bv.x;
                v1.y = acc[mt][nt][3] + bv.y;
                *reinterpret_cast<float2*>(Cf + (size_t)r * N + col) = v0;
                *reinterpret_cast<float2*>(Cf + (size_t)(r + 8) * N + col) = v1;
            }
        }
    } else {
#pragma unroll
        for (int mt = 0; mt < 4; ++mt) {
#pragma unroll
            for (int nt = 0; nt < 4; ++nt) {
                int r = rbase + mt * 16;
                int col = cbase + nt * 8;
                float2 bv = *reinterpret_cast<const float2*>(bias + col);
                float v[4];
                v[0] = acc[mt][nt][0] + bv.x;
                v[1] = acc[mt][nt][1] + bv.y;
                v[2] = acc[mt][nt][2] + bv.x;
                v[3] = acc[mt][nt][3] + bv.y;
                __nv_bfloat16 h0 = __float2bfloat16(v[0]);
                __nv_bfloat16 h1 = __float2bfloat16(v[1]);
                __nv_bfloat16 h2 = __float2bfloat16(v[2]);
                __nv_bfloat16 h3 = __float2bfloat16(v[3]);
                uint32_t hp0 = (uint32_t)__bfloat16_as_ushort(h0) |
                               ((uint32_t)__bfloat16_as_ushort(h1) << 16);
                uint32_t hp1 = (uint32_t)__bfloat16_as_ushort(h2) |
                               ((uint32_t)__bfloat16_as_ushort(h3) << 16);
                uint32_t lp0 = pack_bf16x2(v[0] - __bfloat162float(h0),
                                           v[1] - __bfloat162float(h1));
                uint32_t lp1 = pack_bf16x2(v[2] - __bfloat162float(h2),
                                           v[3] - __bfloat162float(h3));
                *reinterpret_cast<uint32_t*>(Chi + (size_t)r * N + col) = hp0;
                *reinterpret_cast<uint32_t*>(Chi + (size_t)(r + 8) * N + col) = hp1;
                *reinterpret_cast<uint32_t*>(Clo + (size_t)r * N + col) = lp0;
                *reinterpret_cast<uint32_t*>(Clo + (size_t)(r + 8) * N + col) = lp1;
            }
        }
    }
}

// ---------------------------------------------------------------------------
// Tensor-core flash attention (bf16x3, FA2 register pipeline), causal,
// muP scale 1/DHEAD. 128 threads = 4 warps; warp owns 16 query rows.
// BM=64, BN=64, D=128. Reads qkv hi/lo bf16; writes y hi/lo bf16.
// ---------------------------------------------------------------------------
#define ASTR 272                 // smem row stride bytes (128 bf16 + 8 pad)
#define ATILE (64 * ASTR)        // 17408 bytes per tile
#define FSM_QH 0
#define FSM_QL (1 * ATILE)
#define FSM_KH (2 * ATILE)
#define FSM_KL (3 * ATILE)
#define FSM_VH (4 * ATILE)
#define FSM_VL (5 * ATILE)
#define FSMEM  (6 * ATILE)       // 104448

__global__ __launch_bounds__(128, 2)
void flash_mma_kernel(const __nv_bfloat16* __restrict__ qkvh,
                      const __nv_bfloat16* __restrict__ qkvl,
                      __nv_bfloat16* __restrict__ yh,
                      __nv_bfloat16* __restrict__ yl)
{
    extern __shared__ char sm[];
    const uint32_t sbase = smem_u32(sm);
    const int tid = threadIdx.x;
    const int w = tid >> 5;
    const int lane = tid & 31;

    const int qtile = blockIdx.x;            // 0..31
    const int bh = blockIdx.y;               // 0..63
    const int b = bh >> 4;
    const int h = bh & 15;
    const int q0 = qtile * 64;

    // Load Q tile (hi+lo): 64 rows x 128 bf16 each
#pragma unroll
    for (int l = 0; l < 8; ++l) {
        int f = tid + l * 128;               // 0..1023
        int row = f >> 4;
        int c8 = f & 15;
        size_t g = (size_t)(b * SEQ + q0 + row) * QKVDIM + h * DHEAD + c8 * 8;
        uint32_t so = row * ASTR + c8 * 16;
        *reinterpret_cast<uint4*>(sm + FSM_QH + so) =
            *reinterpret_cast<const uint4*>(qkvh + g);
        *reinterpret_cast<uint4*>(sm + FSM_QL + so) =
            *reinterpret_cast<const uint4*>(qkvl + g);
    }

    float o[16][4];
#pragma unroll
    for (int i = 0; i < 16; ++i)
#pragma unroll
        for (int j = 0; j < 4; ++j) o[i][j] = 0.f;
    float mrow[2] = {-CUDART_INF_F, -CUDART_INF_F};
    float lrow[2] = {0.f, 0.f};

    // ldmatrix lane addresses
    const uint32_t qLaneH = sbase + FSM_QH + (w * 16 + (lane & 15)) * ASTR +
                            ((lane & 16) ? 16 : 0);
    const uint32_t qLaneL = qLaneH + (FSM_QL - FSM_QH);
    const uint32_t kLaneH = sbase + FSM_KH +
                            (((lane & 16) ? 8 : 0) + (lane & 7)) * ASTR +
                            ((lane & 8) ? 16 : 0);
    const uint32_t kLaneL = kLaneH + (FSM_KL - FSM_KH);
    const uint32_t vLaneH = sbase + FSM_VH + (lane & 15) * ASTR +
                            ((lane & 16) ? 16 : 0);
    const uint32_t vLaneL = vLaneH + (FSM_VL - FSM_VH);

    const float SCALE_LOG2E = (1.0f / (float)DHEAD) * 1.44269504088896f;

    for (int kt = 0; kt <= qtile; ++kt) {
        const int k0 = kt * 64;
        __syncthreads();   // previous iteration's smem reads done
#pragma unroll
        for (int l = 0; l < 8; ++l) {
            int f = tid + l * 128;
            int row = f >> 4;
            int c8 = f & 15;
            size_t g = (size_t)(b * SEQ + k0 + row) * QKVDIM + h * DHEAD + c8 * 8;
            uint32_t so = row * ASTR + c8 * 16;
            *reinterpret_cast<uint4*>(sm + FSM_KH + so) =
                *reinterpret_cast<const uint4*>(qkvh + DMODEL + g);
            *reinterpret_cast<uint4*>(sm + FSM_KL + so) =
                *reinterpret_cast<const uint4*>(qkvl + DMODEL + g);
            *reinterpret_cast<uint4*>(sm + FSM_VH + so) =
                *reinterpret_cast<const uint4*>(qkvh + 2 * DMODEL + g);
            *reinterpret_cast<uint4*>(sm + FSM_VL + so) =
                *reinterpret_cast<const uint4*>(qkvl + 2 * DMODEL + g);
        }
        __syncthreads();

        // ---- S = Q K^T (3-term) ----
        float sacc[8][4];
#pragma unroll
        for (int i = 0; i < 8; ++i)
#pragma unroll
            for (int j = 0; j < 4; ++j) sacc[i][j] = 0.f;

#pragma unroll
        for (int ks = 0; ks < 8; ++ks) {
            uint32_t ah[4], al[4];
            ldsm4(ah, qLaneH + ks * 32);
            ldsm4(al, qLaneL + ks * 32);
#pragma unroll
            for (int g = 0; g < 4; ++g) {
                uint32_t bhf[4], blf[4];
                ldsm4(bhf, kLaneH + g * (16 * ASTR) + ks * 32);
                ldsm4(blf, kLaneL + g * (16 * ASTR) + ks * 32);
                mma16816(sacc[2 * g],     ah, bhf[0], bhf[1]);
                mma16816(sacc[2 * g + 1], ah, bhf[2], bhf[3]);
                mma16816(sacc[2 * g],     ah, blf[0], blf[1]);
                mma16816(sacc[2 * g + 1], ah, blf[2], blf[3]);
                mma16816(sacc[2 * g],     al, bhf[0], bhf[1]);
                mma16816(sacc[2 * g + 1], al, bhf[2], bhf[3]);
            }
        }

        // ---- causal mask (diagonal tile only) ----
        if (kt == qtile) {
            const int rA = w * 16 + (lane >> 2);
#pragma unroll
            for (int nt = 0; nt < 8; ++nt) {
#pragma unroll
                for (int e = 0; e < 4; ++e) {
                    int col = nt * 8 + (lane & 3) * 2 + (e & 1);
                    int row = rA + ((e & 2) ? 8 : 0);
                    if (col > row) sacc[nt][e] = -CUDART_INF_F;
                }
            }
        }

        // ---- online softmax (rows rA, rA+8); exp2-domain with fused scale ----
        float mx0 = -CUDART_INF_F, mx1 = -CUDART_INF_F;
#pragma unroll
        for (int nt = 0; nt < 8; ++nt) {
            mx0 = fmaxf(mx0, fmaxf(sacc[nt][0], sacc[nt][1]));
            mx1 = fmaxf(mx1, fmaxf(sacc[nt][2], sacc[nt][3]));
        }
        mx0 = fmaxf(mx0, __shfl_xor_sync(0xffffffffu, mx0, 1));
        mx0 = fmaxf(mx0, __shfl_xor_sync(0xffffffffu, mx0, 2));
        mx1 = fmaxf(mx1, __shfl_xor_sync(0xffffffffu, mx1, 1));
        mx1 = fmaxf(mx1, __shfl_xor_sync(0xffffffffu, mx1, 2));
        // running max in exp2-domain units
        float mn0 = fmaxf(mrow[0], mx0 * SCALE_LOG2E);
        float mn1 = fmaxf(mrow[1], mx1 * SCALE_LOG2E);
        float alpha0 = exp2f(mrow[0] - mn0);
        float alpha1 = exp2f(mrow[1] - mn1);
        mrow[0] = mn0; mrow[1] = mn1;

        float sum0 = 0.f, sum1 = 0.f;
#pragma unroll
        for (int nt = 0; nt < 8; ++nt) {
            float p0 = exp2f(sacc[nt][0] * SCALE_LOG2E - mn0);
            float p1 = exp2f(sacc[nt][1] * SCALE_LOG2E - mn0);
            float p2 = exp2f(sacc[nt][2] * SCALE_LOG2E - mn1);
            float p3 = exp2f(sacc[nt][3] * SCALE_LOG2E - mn1);
            sacc[nt][0] = p0; sacc[nt][1] = p1;
            sacc[nt][2] = p2; sacc[nt][3] = p3;
            sum0 += p0 + p1;
            sum1 += p2 + p3;
        }
        sum0 += __shfl_xor_sync(0xffffffffu, sum0, 1);
        sum0 += __shfl_xor_sync(0xffffffffu, sum0, 2);
        sum1 += __shfl_xor_sync(0xffffffffu, sum1, 1);
        sum1 += __shfl_xor_sync(0xffffffffu, sum1, 2);
        lrow[0] = alpha0 * lrow[0] + sum0;
        lrow[1] = alpha1 * lrow[1] + sum1;

        // rescale O
#pragma unroll
        for (int nt = 0; nt < 16; ++nt) {
            o[nt][0] *= alpha0; o[nt][1] *= alpha0;
            o[nt][2] *= alpha1; o[nt][3] *= alpha1;
        }

        // ---- O += P V (3-term: phi*vhi + phi*vlo + plo*vhi) ----
#pragma unroll
        for (int kc = 0; kc < 4; ++kc) {
            // A fragments from S accumulators (C-layout == A-layout per 8-col pair)
            uint32_t pa_h[4], pa_l[4];
#pragma unroll
            for (int half = 0; half < 2; ++half) {
                const float* s2 = sacc[2 * kc + half];
#pragma unroll
                for (int rr = 0; rr < 2; ++rr) {
                    float v0 = s2[rr * 2 + 0];
                    float v1 = s2[rr * 2 + 1];
                    __nv_bfloat16 h0 = __float2bfloat16(v0);
                    __nv_bfloat16 h1 = __float2bfloat16(v1);
                    pa_h[half * 2 + rr] =
                        (uint32_t)__bfloat16_as_ushort(h0) |
                        ((uint32_t)__bfloat16_as_ushort(h1) << 16);
                    pa_l[half * 2 + rr] =
                        pack_bf16x2(v0 - __bfloat162float(h0),
                                    v1 - __bfloat162float(h1));
                }
            }
#pragma unroll
            for (int ng = 0; ng < 8; ++ng) {
                uint32_t vh[4], vl[4];
                ldsm4t(vh, vLaneH + kc * (16 * ASTR) + ng * 32);
                ldsm4t(vl, vLaneL + kc * (16 * ASTR) + ng * 32);
                mma16816(o[2 * ng],     pa_h, vh[0], vh[1]);
                mma16816(o[2 * ng + 1], pa_h, vh[2], vh[3]);
                mma16816(o[2 * ng],     pa_h, vl[0], vl[1]);
                mma16816(o[2 * ng + 1], pa_h, vl[2], vl[3]);
                mma16816(o[2 * ng],     pa_l, vh[0], vh[1]);
                mma16816(o[2 * ng + 1], pa_l, vh[2], vh[3]);
            }
        }
    }

    // ---- epilogue: normalize, split hi/lo, write y ----
    const float inv0 = 1.0f / lrow[0];
    const float inv1 = 1.0f / lrow[1];
    const int rowA = q0 + w * 16 + (lane >> 2);
#pragma unroll
    for (int nt = 0; nt < 16; ++nt) {
        int col = h * DHEAD + nt * 8 + (lane & 3) * 2;
        float v0 = o[nt][0] * inv0, v1 = o[nt][1] * inv0;
        float v2 = o[nt][2] * inv1, v3 = o[nt][3] * inv1;
        __nv_bfloat16 h0 = __float2bfloat16(v0);
        __nv_bfloat16 h1 = __float2bfloat16(v1);
        __nv_bfloat16 h2 = __float2bfloat16(v2);
        __nv_bfloat16 h3 = __float2bfloat16(v3);
        uint32_t hp0 = (uint32_t)__bfloat16_as_ushort(h0) |
                       ((uint32_t)__bfloat16_as_ushort(h1) << 16);
        uint32_t hp1 = (uint32_t)__bfloat16_as_ushort(h2) |
                       ((uint32_t)__bfloat16_as_ushort(h3) << 16);
        uint32_t lp0 = pack_bf16x2(v0 - __bfloat162float(h0),
                                   v1 - __bfloat162float(h1));
        uint32_t lp1 = pack_bf16x2(v2 - __bfloat162float(h2),
                                   v3 - __bfloat162float(h3));
        size_t r0 = (size_t)(b * SEQ + rowA) * DMODEL + col;
        size_t r1 = (size_t)(b * SEQ + rowA + 8) * DMODEL + col;
        *reinterpret_cast<uint32_t*>(yh + r0) = hp0;
        *reinterpret_cast<uint32_t*>(yh + r1) = hp1;
        *reinterpret_cast<uint32_t*>(yl + r0) = lp0;
        *reinterpret_cast<uint32_t*>(yl + r1) = lp1;
    }
}

// ---------------------------------------------------------------------------
// Launch
// ---------------------------------------------------------------------------
extern "C" void kernel_launch(void* const* d_in, const int* in_sizes, int n_in,
                              void* d_out, int out_size)
{
    const float* x     = (const float*)d_in[0];
    const float* W_qkv = (const float*)d_in[1];
    const float* b_qkv = (const float*)d_in[2];
    const float* W_out = (const float*)d_in[3];
    const float* b_out = (const float*)d_in[4];
    float* out = (float*)d_out;

    void *p_xh, *p_xl, *p_wqh, *p_wql, *p_woh, *p_wol, *p_qh, *p_ql, *p_yh, *p_yl;
    cudaGetSymbolAddress(&p_xh, g_x_hi);
    cudaGetSymbolAddress(&p_xl, g_x_lo);
    cudaGetSymbolAddress(&p_wqh, g_wqkv_hi);
    cudaGetSymbolAddress(&p_wql, g_wqkv_lo);
    cudaGetSymbolAddress(&p_woh, g_wout_hi);
    cudaGetSymbolAddress(&p_wol, g_wout_lo);
    cudaGetSymbolAddress(&p_qh, g_qkv_hi);
    cudaGetSymbolAddress(&p_ql, g_qkv_lo);
    cudaGetSymbolAddress(&p_yh, g_y_hi);
    cudaGetSymbolAddress(&p_yl, g_y_lo);

    cudaFuncSetAttribute(gemm_mma_kernel,
                         cudaFuncAttributeMaxDynamicSharedMemorySize, GSMEM);
    cudaFuncSetAttribute(flash_mma_kernel,
                         cudaFuncAttributeMaxDynamicSharedMemorySize, FSMEM);

    // 0) Splits
    {
        int n4 = NTOK * DMODEL / 4;
        split_kernel<<<(n4 + 255) / 256, 256>>>(x, (__nv_bfloat16*)p_xh,
                                                (__nv_bfloat16*)p_xl, n4);
        dim3 blk(32, 8);
        transpose_split_kernel<<<dim3(QKVDIM / 32, DMODEL / 32), blk>>>(
            W_qkv, (__nv_bfloat16*)p_wqh, (__nv_bfloat16*)p_wql, DMODEL, QKVDIM);
        transpose_split_kernel<<<dim3(DMODEL / 32, DMODEL / 32), blk>>>(
            W_out, (__nv_bfloat16*)p_woh, (__nv_bfloat16*)p_wol, DMODEL, DMODEL);
    }

    // 1) QKV projection -> qkv hi/lo bf16 (split epilogue)
    gemm_mma_kernel<<<dim3(QKVDIM / TBN, NTOK / TBM), 256, GSMEM>>>(
        (const __nv_bfloat16*)p_xh, (const __nv_bfloat16*)p_xl,
        (const __nv_bfloat16*)p_wqh, (const __nv_bfloat16*)p_wql,
        b_qkv, nullptr,
        (__nv_bfloat16*)p_qh, (__nv_bfloat16*)p_ql,
        NTOK, QKVDIM, DMODEL);

    // 2) Attention (tensor-core flash) -> y hi/lo bf16
    flash_mma_kernel<<<dim3(SEQ / 64, BATCH * NHEADS), 128, FSMEM>>>(
        (const __nv_bfloat16*)p_qh, (const __nv_bfloat16*)p_ql,
        (__nv_bfloat16*)p_yh, (__nv_bfloat16*)p_yl);

    // 3) Output projection -> fp32 out
    gemm_mma_kernel<<<dim3(DMODEL / TBN, NTOK / TBM), 256, GSMEM>>>(
        (const __nv_bfloat16*)p_yh, (const __nv_bfloat16*)p_yl,
        (const __nv_bfloat16*)p_woh, (const __nv_bfloat16*)p_wol,
        b_out, out, nullptr, nullptr,
        NTOK, DMODEL, DMODEL);
}

// round 5
// speedup vs baseline: 4.5444x; 1.2625x over previous
#include <cuda_runtime.h>
#include <cuda_fp16.h>
#include <math_constants.h>
#include <cstdint>

// Problem constants
#define BATCH   4
#define SEQ     2048
#define DMODEL  2048
#define NHEADS  16
#define DHEAD   128
#define QKVDIM  (3 * DMODEL)       // 6144
#define NTOK    (BATCH * SEQ)      // 8192

// ---------------------------------------------------------------------------
// Scratch (__device__ globals; no cudaMalloc allowed)
// ---------------------------------------------------------------------------
__device__ __half g_x_hi[(size_t)NTOK * DMODEL];
__device__ __half g_x_lo[(size_t)NTOK * DMODEL];
__device__ __half g_wqkv_hi[(size_t)QKVDIM * DMODEL];  // transposed [N,K]
__device__ __half g_wout_hi[(size_t)DMODEL * DMODEL];  // transposed [N,K]
__device__ __half g_qkv_hi[(size_t)NTOK * QKVDIM];
__device__ __half g_qkv_lo[(size_t)NTOK * QKVDIM];
__device__ __half g_y_hi[(size_t)NTOK * DMODEL];
__device__ __half g_y_lo[(size_t)NTOK * DMODEL];

// ---------------------------------------------------------------------------
// Warp-MMA / async-copy helpers (plain PTX, compute_103-safe)
// ---------------------------------------------------------------------------
__device__ __forceinline__ uint32_t smem_u32(const void* p) {
    uint32_t a;
    asm("{ .reg .u64 t; cvta.to.shared.u64 t, %1; cvt.u32.u64 %0, t; }"
        : "=r"(a) : "l"(p));
    return a;
}

__device__ __forceinline__ void ldsm4(uint32_t r[4], uint32_t addr) {
    asm volatile("ldmatrix.sync.aligned.m8n8.x4.shared.b16 {%0,%1,%2,%3}, [%4];"
                 : "=r"(r[0]), "=r"(r[1]), "=r"(r[2]), "=r"(r[3]) : "r"(addr));
}
__device__ __forceinline__ void ldsm4t(uint32_t r[4], uint32_t addr) {
    asm volatile("ldmatrix.sync.aligned.m8n8.x4.trans.shared.b16 {%0,%1,%2,%3}, [%4];"
                 : "=r"(r[0]), "=r"(r[1]), "=r"(r[2]), "=r"(r[3]) : "r"(addr));
}

__device__ __forceinline__ void mma16816f(float c[4], const uint32_t a[4],
                                          uint32_t b0, uint32_t b1) {
    asm volatile(
        "mma.sync.aligned.m16n8k16.row.col.f32.f16.f16.f32 "
        "{%0,%1,%2,%3}, {%4,%5,%6,%7}, {%8,%9}, {%0,%1,%2,%3};"
        : "+f"(c[0]), "+f"(c[1]), "+f"(c[2]), "+f"(c[3])
        : "r"(a[0]), "r"(a[1]), "r"(a[2]), "r"(a[3]), "r"(b0), "r"(b1));
}

// pack two fp32 -> f16x2 (first arg in bits [0,16))
__device__ __forceinline__ uint32_t pack_f16x2(float lo, float hi) {
    uint32_t r;
    asm("cvt.rn.f16x2.f32 %0, %1, %2;" : "=r"(r) : "f"(hi), "f"(lo));
    return r;
}

__device__ __forceinline__ void cp16(uint32_t dst, const void* src) {
    asm volatile("cp.async.cg.shared.global [%0], [%1], 16;"
                 :: "r"(dst), "l"(src));
}
#define CP_COMMIT() asm volatile("cp.async.commit_group;" ::: "memory")
#define CP_WAIT0()  asm volatile("cp.async.wait_group 0;" ::: "memory")
#define CP_WAIT1()  asm volatile("cp.async.wait_group 1;" ::: "memory")

// ---------------------------------------------------------------------------
// Split kernels: fp32 -> (hi fp16, lo fp16) with lo = f16(v - f32(hi))
// ---------------------------------------------------------------------------
__global__ void split_kernel(const float* __restrict__ in,
                             __half* __restrict__ hi,
                             __half* __restrict__ lo, int n4)
{
    int i = blockIdx.x * blockDim.x + threadIdx.x;
    if (i >= n4) return;
    float4 v = reinterpret_cast<const float4*>(in)[i];
    float vv[4] = {v.x, v.y, v.z, v.w};
    unsigned short hraw[4], lraw[4];
#pragma unroll
    for (int j = 0; j < 4; ++j) {
        __half h = __float2half_rn(vv[j]);
        __half l = __float2half_rn(vv[j] - __half2float(h));
        hraw[j] = __half_as_ushort(h);
        lraw[j] = __half_as_ushort(l);
    }
    reinterpret_cast<uint64_t*>(hi)[i] = *reinterpret_cast<uint64_t*>(hraw);
    reinterpret_cast<uint64_t*>(lo)[i] = *reinterpret_cast<uint64_t*>(lraw);
}

// W [K,N] fp32 -> Thi [N,K] fp16 (transpose + round; hi only)
__global__ void transpose_cvt_kernel(const float* __restrict__ W,
                                     __half* __restrict__ Thi,
                                     int K, int N)
{
    __shared__ float tile[32][33];
    int nx = blockIdx.x * 32 + threadIdx.x;
    int k0 = blockIdx.y * 32;
#pragma unroll
    for (int j = 0; j < 32; j += 8)
        tile[threadIdx.y + j][threadIdx.x] = W[(size_t)(k0 + threadIdx.y + j) * N + nx];
    __syncthreads();
    int k = k0 + threadIdx.x;
    int nbase = blockIdx.x * 32 + threadIdx.y;
#pragma unroll
    for (int j = 0; j < 32; j += 8)
        Thi[(size_t)(nbase + j) * K + k] = __float2half_rn(tile[threadIdx.x][threadIdx.y + j]);
}

// ---------------------------------------------------------------------------
// fp16 2-term GEMM via warp mma.sync with cp.async double buffering:
//   C[M,N] = (Ahi + Alo)[M,K] @ Bhi[N,K]^T + bias
// CTA tile 128x128, 8 warps (2 M x 4 N), warp tile 64x32, K-chunk 64.
// Epilogue: fp32 write (Cf) OR fp16 hi/lo split write (Chi/Clo).
// ---------------------------------------------------------------------------
#define TBM 128
#define TBN 128
#define TKC 64
#define STRB 144                 // smem row stride bytes (64 fp16 + 16 pad)
#define TILEB (128 * STRB)       // 18432
#define STAGEB (3 * TILEB)       // 55296: [Ahi][Alo][Bhi]
#define GSMEM (2 * STAGEB)       // 110592

__global__ __launch_bounds__(256, 2)
void gemm_mma_kernel(const __half* __restrict__ Ahi,
                     const __half* __restrict__ Alo,
                     const __half* __restrict__ Bhi,
                     const float* __restrict__ bias,
                     float* __restrict__ Cf,
                     __half* __restrict__ Chi,
                     __half* __restrict__ Clo,
                     int M, int N, int K)
{
    extern __shared__ char sm[];
    const uint32_t sbase = smem_u32(sm);
    const int tid = threadIdx.x;
    const int wid = tid >> 5;
    const int lane = tid & 31;
    const int m0 = blockIdx.y * TBM;
    const int n0 = blockIdx.x * TBN;
    const int wm = wid & 1;
    const int wn = wid >> 1;

    // precomputed per-thread load geometry (4 lines per tile per thread)
    const int lrowA[4] = { (tid + 0) >> 3, (tid + 256) >> 3,
                           (tid + 512) >> 3, (tid + 768) >> 3 };
    const int lc16 = tid & 7;

    float acc[4][4][4];
#pragma unroll
    for (int i = 0; i < 4; ++i)
#pragma unroll
        for (int j = 0; j < 4; ++j)
#pragma unroll
            for (int k = 0; k < 4; ++k) acc[i][j][k] = 0.f;

    const int arow = lane & 15;
    const int akb  = (lane & 16) ? 16 : 0;
    const int brow = ((lane & 16) ? 8 : 0) + (lane & 7);
    const int bkb  = (lane & 8) ? 16 : 0;

    const uint32_t aHiL = sbase + (wm * 64 + arow) * STRB + akb;            // +stage
    const uint32_t aLoL = aHiL + TILEB;
    const uint32_t bHiL = sbase + 2 * TILEB + (wn * 32 + brow) * STRB + bkb;

    const int nchunk = K / TKC;

    // --- issue helper (inlined twice) ---
#define GEMM_ISSUE(CHUNK, STAGE)                                              \
    {                                                                         \
        const int k0_ = (CHUNK) * TKC;                                        \
        const uint32_t sb_ = sbase + (STAGE) * STAGEB;                        \
        _Pragma("unroll")                                                     \
        for (int l = 0; l < 4; ++l) {                                         \
            int row = lrowA[l];                                               \
            uint32_t so = row * STRB + lc16 * 16;                             \
            size_t ga = (size_t)(m0 + row) * K + k0_ + lc16 * 8;              \
            size_t gb = (size_t)(n0 + row) * K + k0_ + lc16 * 8;              \
            cp16(sb_ + so, Ahi + ga);                                         \
            cp16(sb_ + TILEB + so, Alo + ga);                                 \
            cp16(sb_ + 2 * TILEB + so, Bhi + gb);                             \
        }                                                                     \
    }

    GEMM_ISSUE(0, 0);
    CP_COMMIT();

    for (int c = 0; c < nchunk; ++c) {
        if (c + 1 < nchunk) {
            GEMM_ISSUE(c + 1, (c + 1) & 1);
            CP_COMMIT();
            CP_WAIT1();
        } else {
            CP_WAIT0();
        }
        __syncthreads();

        const uint32_t stoff = (uint32_t)(c & 1) * STAGEB;
#pragma unroll
        for (int ks = 0; ks < 4; ++ks) {
            uint32_t ah[4][4], al[4][4], bh[2][4];
#pragma unroll
            for (int mt = 0; mt < 4; ++mt) {
                ldsm4(ah[mt], aHiL + stoff + mt * (16 * STRB) + ks * 32);
                ldsm4(al[mt], aLoL + stoff + mt * (16 * STRB) + ks * 32);
            }
#pragma unroll
            for (int np = 0; np < 2; ++np)
                ldsm4(bh[np], bHiL + stoff + np * (16 * STRB) + ks * 32);
#pragma unroll
            for (int mt = 0; mt < 4; ++mt)
#pragma unroll
                for (int nt = 0; nt < 4; ++nt)
                    mma16816f(acc[mt][nt], ah[mt],
                              bh[nt >> 1][(nt & 1) * 2], bh[nt >> 1][(nt & 1) * 2 + 1]);
#pragma unroll
            for (int mt = 0; mt < 4; ++mt)
#pragma unroll
                for (int nt = 0; nt < 4; ++nt)
                    mma16816f(acc[mt][nt], al[mt],
                              bh[nt >> 1][(nt & 1) * 2], bh[nt >> 1][(nt & 1) * 2 + 1]);
        }
        __syncthreads();
    }
#undef GEMM_ISSUE

    // Epilogue
    const int rbase = m0 + wm * 64 + (lane >> 2);
    const int cbase = n0 + wn * 32 + (lane & 3) * 2;
    if (Cf) {
#pragma unroll
        for (int mt = 0; mt < 4; ++mt) {
#pragma unroll
            for (int nt = 0; nt < 4; ++nt) {
                int r = rbase + mt * 16;
                int col = cbase + nt * 8;
                float2 bv = *reinterpret_cast<const float2*>(bias + col);
                float2 v0, v1;
                v0.x = acc[mt][nt][0] + bv.x;
                v0.y = acc[mt][nt][1] + bv.y;
                v1.x = acc[mt][nt][2] + bv.x;
                v1.y = acc[mt][nt][3] + bv.y;
                *reinterpret_cast<float2*>(Cf + (size_t)r * N + col) = v0;
                *reinterpret_cast<float2*>(Cf + (size_t)(r + 8) * N + col) = v1;
            }
        }
    } else {
#pragma unroll
        for (int mt = 0; mt < 4; ++mt) {
#pragma unroll
            for (int nt = 0; nt < 4; ++nt) {
                int r = rbase + mt * 16;
                int col = cbase + nt * 8;
                float2 bv = *reinterpret_cast<const float2*>(bias + col);
                float v[4];
                v[0] = acc[mt][nt][0] + bv.x;
                v[1] = acc[mt][nt][1] + bv.y;
                v[2] = acc[mt][nt][2] + bv.x;
                v[3] = acc[mt][nt][3] + bv.y;
                __half h0 = __float2half_rn(v[0]);
                __half h1 = __float2half_rn(v[1]);
                __half h2 = __float2half_rn(v[2]);
                __half h3 = __float2half_rn(v[3]);
                uint32_t hp0 = (uint32_t)__half_as_ushort(h0) |
                               ((uint32_t)__half_as_ushort(h1) << 16);
                uint32_t hp1 = (uint32_t)__half_as_ushort(h2) |
                               ((uint32_t)__half_as_ushort(h3) << 16);
                uint32_t lp0 = pack_f16x2(v[0] - __half2float(h0),
                                          v[1] - __half2float(h1));
                uint32_t lp1 = pack_f16x2(v[2] - __half2float(h2),
                                          v[3] - __half2float(h3));
                *reinterpret_cast<uint32_t*>(Chi + (size_t)r * N + col) = hp0;
                *reinterpret_cast<uint32_t*>(Chi + (size_t)(r + 8) * N + col) = hp1;
                *reinterpret_cast<uint32_t*>(Clo + (size_t)r * N + col) = lp0;
                *reinterpret_cast<uint32_t*>(Clo + (size_t)(r + 8) * N + col) = lp1;
            }
        }
    }
}

// ---------------------------------------------------------------------------
// Tensor-core flash attention (fp16 3-term, FA2 register pipeline), causal,
// muP scale 1/DHEAD. 128 threads = 4 warps; warp owns 16 query rows.
// BM=64, BN=64, D=128. Reads qkv hi/lo fp16; writes y hi/lo fp16.
// ---------------------------------------------------------------------------
#define ASTR 272                 // smem row stride bytes (128 fp16 + 16 pad)
#define ATILE (64 * ASTR)        // 17408 bytes per tile
#define FSM_QH 0
#define FSM_QL (1 * ATILE)
#define FSM_KH (2 * ATILE)
#define FSM_KL (3 * ATILE)
#define FSM_VH (4 * ATILE)
#define FSM_VL (5 * ATILE)
#define FSMEM  (6 * ATILE)       // 104448

__global__ __launch_bounds__(128, 2)
void flash_mma_kernel(const __half* __restrict__ qkvh,
                      const __half* __restrict__ qkvl,
                      __half* __restrict__ yh,
                      __half* __restrict__ yl)
{
    extern __shared__ char sm[];
    const uint32_t sbase = smem_u32(sm);
    const int tid = threadIdx.x;
    const int w = tid >> 5;
    const int lane = tid & 31;

    const int qtile = blockIdx.x;
    const int bh = blockIdx.y;
    const int b = bh >> 4;
    const int h = bh & 15;
    const int q0 = qtile * 64;

#pragma unroll
    for (int l = 0; l < 8; ++l) {
        int f = tid + l * 128;
        int row = f >> 4;
        int c8 = f & 15;
        size_t g = (size_t)(b * SEQ + q0 + row) * QKVDIM + h * DHEAD + c8 * 8;
        uint32_t so = row * ASTR + c8 * 16;
        *reinterpret_cast<uint4*>(sm + FSM_QH + so) =
            *reinterpret_cast<const uint4*>(qkvh + g);
        *reinterpret_cast<uint4*>(sm + FSM_QL + so) =
            *reinterpret_cast<const uint4*>(qkvl + g);
    }

    float o[16][4];
#pragma unroll
    for (int i = 0; i < 16; ++i)
#pragma unroll
        for (int j = 0; j < 4; ++j) o[i][j] = 0.f;
    float mrow[2] = {-CUDART_INF_F, -CUDART_INF_F};
    float lrow[2] = {0.f, 0.f};

    const uint32_t qLaneH = sbase + FSM_QH + (w * 16 + (lane & 15)) * ASTR +
                            ((lane & 16) ? 16 : 0);
    const uint32_t qLaneL = qLaneH + (FSM_QL - FSM_QH);
    const uint32_t kLaneH = sbase + FSM_KH +
                            (((lane & 16) ? 8 : 0) + (lane & 7)) * ASTR +
                            ((lane & 8) ? 16 : 0);
    const uint32_t kLaneL = kLaneH + (FSM_KL - FSM_KH);
    const uint32_t vLaneH = sbase + FSM_VH + (lane & 15) * ASTR +
                            ((lane & 16) ? 16 : 0);
    const uint32_t vLaneL = vLaneH + (FSM_VL - FSM_VH);

    const float SCALE_LOG2E = (1.0f / (float)DHEAD) * 1.44269504088896f;

    for (int kt = 0; kt <= qtile; ++kt) {
        const int k0 = kt * 64;
        __syncthreads();
#pragma unroll
        for (int l = 0; l < 8; ++l) {
            int f = tid + l * 128;
            int row = f >> 4;
            int c8 = f & 15;
            size_t g = (size_t)(b * SEQ + k0 + row) * QKVDIM + h * DHEAD + c8 * 8;
            uint32_t so = row * ASTR + c8 * 16;
            *reinterpret_cast<uint4*>(sm + FSM_KH + so) =
                *reinterpret_cast<const uint4*>(qkvh + DMODEL + g);
            *reinterpret_cast<uint4*>(sm + FSM_KL + so) =
                *reinterpret_cast<const uint4*>(qkvl + DMODEL + g);
            *reinterpret_cast<uint4*>(sm + FSM_VH + so) =
                *reinterpret_cast<const uint4*>(qkvh + 2 * DMODEL + g);
            *reinterpret_cast<uint4*>(sm + FSM_VL + so) =
                *reinterpret_cast<const uint4*>(qkvl + 2 * DMODEL + g);
        }
        __syncthreads();

        // ---- S = Q K^T (3-term fp16: qh*kh + qh*kl + ql*kh) ----
        float sacc[8][4];
#pragma unroll
        for (int i = 0; i < 8; ++i)
#pragma unroll
            for (int j = 0; j < 4; ++j) sacc[i][j] = 0.f;

#pragma unroll
        for (int ks = 0; ks < 8; ++ks) {
            uint32_t ah[4], al[4];
            ldsm4(ah, qLaneH + ks * 32);
            ldsm4(al, qLaneL + ks * 32);
#pragma unroll
            for (int g = 0; g < 4; ++g) {
                uint32_t bhf[4], blf[4];
                ldsm4(bhf, kLaneH + g * (16 * ASTR) + ks * 32);
                ldsm4(blf, kLaneL + g * (16 * ASTR) + ks * 32);
                mma16816f(sacc[2 * g],     ah, bhf[0], bhf[1]);
                mma16816f(sacc[2 * g + 1], ah, bhf[2], bhf[3]);
                mma16816f(sacc[2 * g],     ah, blf[0], blf[1]);
                mma16816f(sacc[2 * g + 1], ah, blf[2], blf[3]);
                mma16816f(sacc[2 * g],     al, bhf[0], bhf[1]);
                mma16816f(sacc[2 * g + 1], al, bhf[2], bhf[3]);
            }
        }

        if (kt == qtile) {
            const int rA = w * 16 + (lane >> 2);
#pragma unroll
            for (int nt = 0; nt < 8; ++nt) {
#pragma unroll
                for (int e = 0; e < 4; ++e) {
                    int col = nt * 8 + (lane & 3) * 2 + (e & 1);
                    int row = rA + ((e & 2) ? 8 : 0);
                    if (col > row) sacc[nt][e] = -CUDART_INF_F;
                }
            }
        }

        // ---- online softmax ----
        float mx0 = -CUDART_INF_F, mx1 = -CUDART_INF_F;
#pragma unroll
        for (int nt = 0; nt < 8; ++nt) {
            mx0 = fmaxf(mx0, fmaxf(sacc[nt][0], sacc[nt][1]));
            mx1 = fmaxf(mx1, fmaxf(sacc[nt][2], sacc[nt][3]));
        }
        mx0 = fmaxf(mx0, __shfl_xor_sync(0xffffffffu, mx0, 1));
        mx0 = fmaxf(mx0, __shfl_xor_sync(0xffffffffu, mx0, 2));
        mx1 = fmaxf(mx1, __shfl_xor_sync(0xffffffffu, mx1, 1));
        mx1 = fmaxf(mx1, __shfl_xor_sync(0xffffffffu, mx1, 2));
        float mn0 = fmaxf(mrow[0], mx0 * SCALE_LOG2E);
        float mn1 = fmaxf(mrow[1], mx1 * SCALE_LOG2E);
        float alpha0 = exp2f(mrow[0] - mn0);
        float alpha1 = exp2f(mrow[1] - mn1);
        mrow[0] = mn0; mrow[1] = mn1;

        float sum0 = 0.f, sum1 = 0.f;
#pragma unroll
        for (int nt = 0; nt < 8; ++nt) {
            float p0 = exp2f(sacc[nt][0] * SCALE_LOG2E - mn0);
            float p1 = exp2f(sacc[nt][1] * SCALE_LOG2E - mn0);
            float p2 = exp2f(sacc[nt][2] * SCALE_LOG2E - mn1);
            float p3 = exp2f(sacc[nt][3] * SCALE_LOG2E - mn1);
            sacc[nt][0] = p0; sacc[nt][1] = p1;
            sacc[nt][2] = p2; sacc[nt][3] = p3;
            sum0 += p0 + p1;
            sum1 += p2 + p3;
        }
        sum0 += __shfl_xor_sync(0xffffffffu, sum0, 1);
        sum0 += __shfl_xor_sync(0xffffffffu, sum0, 2);
        sum1 += __shfl_xor_sync(0xffffffffu, sum1, 1);
        sum1 += __shfl_xor_sync(0xffffffffu, sum1, 2);
        lrow[0] = alpha0 * lrow[0] + sum0;
        lrow[1] = alpha1 * lrow[1] + sum1;

#pragma unroll
        for (int nt = 0; nt < 16; ++nt) {
            o[nt][0] *= alpha0; o[nt][1] *= alpha0;
            o[nt][2] *= alpha1; o[nt][3] *= alpha1;
        }

        // ---- O += P V (3-term: ph*vh + ph*vl + pl*vh) ----
#pragma unroll
        for (int kc = 0; kc < 4; ++kc) {
            uint32_t pa_h[4], pa_l[4];
#pragma unroll
            for (int half = 0; half < 2; ++half) {
                const float* s2 = sacc[2 * kc + half];
#pragma unroll
                for (int rr = 0; rr < 2; ++rr) {
                    float v0 = s2[rr * 2 + 0];
                    float v1 = s2[rr * 2 + 1];
                    __half h0 = __float2half_rn(v0);
                    __half h1 = __float2half_rn(v1);
                    pa_h[half * 2 + rr] =
                        (uint32_t)__half_as_ushort(h0) |
                        ((uint32_t)__half_as_ushort(h1) << 16);
                    pa_l[half * 2 + rr] =
                        pack_f16x2(v0 - __half2float(h0),
                                   v1 - __half2float(h1));
                }
            }
#pragma unroll
            for (int ng = 0; ng < 8; ++ng) {
                uint32_t vh[4], vl[4];
                ldsm4t(vh, vLaneH + kc * (16 * ASTR) + ng * 32);
                ldsm4t(vl, vLaneL + kc * (16 * ASTR) + ng * 32);
                mma16816f(o[2 * ng],     pa_h, vh[0], vh[1]);
                mma16816f(o[2 * ng + 1], pa_h, vh[2], vh[3]);
                mma16816f(o[2 * ng],     pa_h, vl[0], vl[1]);
                mma16816f(o[2 * ng + 1], pa_h, vl[2], vl[3]);
                mma16816f(o[2 * ng],     pa_l, vh[0], vh[1]);
                mma16816f(o[2 * ng + 1], pa_l, vh[2], vh[3]);
            }
        }
    }

    // ---- epilogue ----
    const float inv0 = 1.0f / lrow[0];
    const float inv1 = 1.0f / lrow[1];
    const int rowA = q0 + w * 16 + (lane >> 2);
#pragma unroll
    for (int nt = 0; nt < 16; ++nt) {
        int col = h * DHEAD + nt * 8 + (lane & 3) * 2;
        float v0 = o[nt][0] * inv0, v1 = o[nt][1] * inv0;
        float v2 = o[nt][2] * inv1, v3 = o[nt][3] * inv1;
        __half h0 = __float2half_rn(v0);
        __half h1 = __float2half_rn(v1);
        __half h2 = __float2half_rn(v2);
        __half h3 = __float2half_rn(v3);
        uint32_t hp0 = (uint32_t)__half_as_ushort(h0) |
                       ((uint32_t)__half_as_ushort(h1) << 16);
        uint32_t hp1 = (uint32_t)__half_as_ushort(h2) |
                       ((uint32_t)__half_as_ushort(h3) << 16);
        uint32_t lp0 = pack_f16x2(v0 - __half2float(h0),
                                  v1 - __half2float(h1));
        uint32_t lp1 = pack_f16x2(v2 - __half2float(h2),
                                  v3 - __half2float(h3));
        size_t r0 = (size_t)(b * SEQ + rowA) * DMODEL + col;
        size_t r1 = (size_t)(b * SEQ + rowA + 8) * DMODEL + col;
        *reinterpret_cast<uint32_t*>(yh + r0) = hp0;
        *reinterpret_cast<uint32_t*>(yh + r1) = hp1;
        *reinterpret_cast<uint32_t*>(yl + r0) = lp0;
        *reinterpret_cast<uint32_t*>(yl + r1) = lp1;
    }
}

// ---------------------------------------------------------------------------
// Launch
// ---------------------------------------------------------------------------
extern "C" void kernel_launch(void* const* d_in, const int* in_sizes, int n_in,
                              void* d_out, int out_size)
{
    const float* x     = (const float*)d_in[0];
    const float* W_qkv = (const float*)d_in[1];
    const float* b_qkv = (const float*)d_in[2];
    const float* W_out = (const float*)d_in[3];
    const float* b_out = (const float*)d_in[4];
    float* out = (float*)d_out;

    void *p_xh, *p_xl, *p_wqh, *p_woh, *p_qh, *p_ql, *p_yh, *p_yl;
    cudaGetSymbolAddress(&p_xh, g_x_hi);
    cudaGetSymbolAddress(&p_xl, g_x_lo);
    cudaGetSymbolAddress(&p_wqh, g_wqkv_hi);
    cudaGetSymbolAddress(&p_woh, g_wout_hi);
    cudaGetSymbolAddress(&p_qh, g_qkv_hi);
    cudaGetSymbolAddress(&p_ql, g_qkv_lo);
    cudaGetSymbolAddress(&p_yh, g_y_hi);
    cudaGetSymbolAddress(&p_yl, g_y_lo);

    cudaFuncSetAttribute(gemm_mma_kernel,
                         cudaFuncAttributeMaxDynamicSharedMemorySize, GSMEM);
    cudaFuncSetAttribute(flash_mma_kernel,
                         cudaFuncAttributeMaxDynamicSharedMemorySize, FSMEM);

    // 0) Splits
    {
        int n4 = NTOK * DMODEL / 4;
        split_kernel<<<(n4 + 255) / 256, 256>>>(x, (__half*)p_xh, (__half*)p_xl, n4);
        dim3 blk(32, 8);
        transpose_cvt_kernel<<<dim3(QKVDIM / 32, DMODEL / 32), blk>>>(
            W_qkv, (__half*)p_wqh, DMODEL, QKVDIM);
        transpose_cvt_kernel<<<dim3(DMODEL / 32, DMODEL / 32), blk>>>(
            W_out, (__half*)p_woh, DMODEL, DMODEL);
    }

    // 1) QKV projection -> qkv hi/lo fp16 (split epilogue)
    gemm_mma_kernel<<<dim3(QKVDIM / TBN, NTOK / TBM), 256, GSMEM>>>(
        (const __half*)p_xh, (const __half*)p_xl, (const __half*)p_wqh,
        b_qkv, nullptr,
        (__half*)p_qh, (__half*)p_ql,
        NTOK, QKVDIM, DMODEL);

    // 2) Attention (tensor-core flash, fp16 3-term) -> y hi/lo fp16
    flash_mma_kernel<<<dim3(SEQ / 64, BATCH * NHEADS), 128, FSMEM>>>(
        (const __half*)p_qh, (const __half*)p_ql,
        (__half*)p_yh, (__half*)p_yl);

    // 3) Output projection -> fp32 out
    gemm_mma_kernel<<<dim3(DMODEL / TBN, NTOK / TBM), 256, GSMEM>>>(
        (const __half*)p_yh, (const __half*)p_yl, (const __half*)p_woh,
        b_out, out, nullptr, nullptr,
        NTOK, DMODEL, DMODEL);
}

// round 6
// speedup vs baseline: 4.9560x; 1.0906x over previous
#include <cuda_runtime.h>
#include <cuda_fp16.h>
#include <math_constants.h>
#include <cstdint>

// Problem constants
#define BATCH   4
#define SEQ     2048
#define DMODEL  2048
#define NHEADS  16
#define DHEAD   128
#define QKVDIM  (3 * DMODEL)       // 6144
#define NTOK    (BATCH * SEQ)      // 8192

// ---------------------------------------------------------------------------
// Scratch (__device__ globals; no cudaMalloc allowed)
// ---------------------------------------------------------------------------
__device__ __half g_x_hi[(size_t)NTOK * DMODEL];
__device__ __half g_x_lo[(size_t)NTOK * DMODEL];
__device__ __half g_wqkv_hi[(size_t)QKVDIM * DMODEL];  // transposed [N,K]
__device__ __half g_wout_hi[(size_t)DMODEL * DMODEL];  // transposed [N,K]
__device__ __half g_qkv_hi[(size_t)NTOK * QKVDIM];
__device__ __half g_qkv_lo[(size_t)NTOK * QKVDIM];
__device__ __half g_y_hi[(size_t)NTOK * DMODEL];
__device__ __half g_y_lo[(size_t)NTOK * DMODEL];

// ---------------------------------------------------------------------------
// Warp-MMA / async-copy helpers (plain PTX, compute_103-safe)
// ---------------------------------------------------------------------------
__device__ __forceinline__ uint32_t smem_u32(const void* p) {
    uint32_t a;
    asm("{ .reg .u64 t; cvta.to.shared.u64 t, %1; cvt.u32.u64 %0, t; }"
        : "=r"(a) : "l"(p));
    return a;
}

__device__ __forceinline__ void ldsm4(uint32_t r[4], uint32_t addr) {
    asm volatile("ldmatrix.sync.aligned.m8n8.x4.shared.b16 {%0,%1,%2,%3}, [%4];"
                 : "=r"(r[0]), "=r"(r[1]), "=r"(r[2]), "=r"(r[3]) : "r"(addr));
}
__device__ __forceinline__ void ldsm4t(uint32_t r[4], uint32_t addr) {
    asm volatile("ldmatrix.sync.aligned.m8n8.x4.trans.shared.b16 {%0,%1,%2,%3}, [%4];"
                 : "=r"(r[0]), "=r"(r[1]), "=r"(r[2]), "=r"(r[3]) : "r"(addr));
}

__device__ __forceinline__ void mma16816f(float c[4], const uint32_t a[4],
                                          uint32_t b0, uint32_t b1) {
    asm volatile(
        "mma.sync.aligned.m16n8k16.row.col.f32.f16.f16.f32 "
        "{%0,%1,%2,%3}, {%4,%5,%6,%7}, {%8,%9}, {%0,%1,%2,%3};"
        : "+f"(c[0]), "+f"(c[1]), "+f"(c[2]), "+f"(c[3])
        : "r"(a[0]), "r"(a[1]), "r"(a[2]), "r"(a[3]), "r"(b0), "r"(b1));
}

// pack two fp32 -> f16x2 (first arg in bits [0,16))
__device__ __forceinline__ uint32_t pack_f16x2(float lo, float hi) {
    uint32_t r;
    asm("cvt.rn.f16x2.f32 %0, %1, %2;" : "=r"(r) : "f"(hi), "f"(lo));
    return r;
}

__device__ __forceinline__ void cp16(uint32_t dst, const void* src) {
    asm volatile("cp.async.cg.shared.global [%0], [%1], 16;"
                 :: "r"(dst), "l"(src));
}
#define CP_COMMIT() asm volatile("cp.async.commit_group;" ::: "memory")
#define CP_WAIT0()  asm volatile("cp.async.wait_group 0;" ::: "memory")
#define CP_WAIT1()  asm volatile("cp.async.wait_group 1;" ::: "memory")

// ---------------------------------------------------------------------------
// Split kernels: fp32 -> (hi fp16, lo fp16) with lo = f16(v - f32(hi))
// ---------------------------------------------------------------------------
__global__ void split_kernel(const float* __restrict__ in,
                             __half* __restrict__ hi,
                             __half* __restrict__ lo, int n4)
{
    int i = blockIdx.x * blockDim.x + threadIdx.x;
    if (i >= n4) return;
    float4 v = reinterpret_cast<const float4*>(in)[i];
    float vv[4] = {v.x, v.y, v.z, v.w};
    unsigned short hraw[4], lraw[4];
#pragma unroll
    for (int j = 0; j < 4; ++j) {
        __half h = __float2half_rn(vv[j]);
        __half l = __float2half_rn(vv[j] - __half2float(h));
        hraw[j] = __half_as_ushort(h);
        lraw[j] = __half_as_ushort(l);
    }
    reinterpret_cast<uint64_t*>(hi)[i] = *reinterpret_cast<uint64_t*>(hraw);
    reinterpret_cast<uint64_t*>(lo)[i] = *reinterpret_cast<uint64_t*>(lraw);
}

// W [K,N] fp32 -> Thi [N,K] fp16 (transpose + round; hi only)
__global__ void transpose_cvt_kernel(const float* __restrict__ W,
                                     __half* __restrict__ Thi,
                                     int K, int N)
{
    __shared__ float tile[32][33];
    int nx = blockIdx.x * 32 + threadIdx.x;
    int k0 = blockIdx.y * 32;
#pragma unroll
    for (int j = 0; j < 32; j += 8)
        tile[threadIdx.y + j][threadIdx.x] = W[(size_t)(k0 + threadIdx.y + j) * N + nx];
    __syncthreads();
    int k = k0 + threadIdx.x;
    int nbase = blockIdx.x * 32 + threadIdx.y;
#pragma unroll
    for (int j = 0; j < 32; j += 8)
        Thi[(size_t)(nbase + j) * K + k] = __float2half_rn(tile[threadIdx.x][threadIdx.y + j]);
}

// ---------------------------------------------------------------------------
// fp16 2-term GEMM via warp mma.sync with cp.async double buffering:
//   C[M,N] = (Ahi + Alo)[M,K] @ Bhi[N,K]^T + bias
// CTA tile 128x128, 8 warps (2 M x 4 N), warp tile 64x32, K-chunk 64.
// Inner step interleaves hi-MMAs with Alo ldmatrix.
// ---------------------------------------------------------------------------
#define TBM 128
#define TBN 128
#define TKC 64
#define STRB 144                 // smem row stride bytes (64 fp16 + 16 pad)
#define TILEB (128 * STRB)       // 18432
#define STAGEB (3 * TILEB)       // 55296: [Ahi][Alo][Bhi]
#define GSMEM (2 * STAGEB)       // 110592

__global__ __launch_bounds__(256, 2)
void gemm_mma_kernel(const __half* __restrict__ Ahi,
                     const __half* __restrict__ Alo,
                     const __half* __restrict__ Bhi,
                     const float* __restrict__ bias,
                     float* __restrict__ Cf,
                     __half* __restrict__ Chi,
                     __half* __restrict__ Clo,
                     int M, int N, int K)
{
    extern __shared__ char sm[];
    const uint32_t sbase = smem_u32(sm);
    const int tid = threadIdx.x;
    const int wid = tid >> 5;
    const int lane = tid & 31;
    const int m0 = blockIdx.y * TBM;
    const int n0 = blockIdx.x * TBN;
    const int wm = wid & 1;
    const int wn = wid >> 1;

    const int lrowA[4] = { (tid + 0) >> 3, (tid + 256) >> 3,
                           (tid + 512) >> 3, (tid + 768) >> 3 };
    const int lc16 = tid & 7;

    float acc[4][4][4];
#pragma unroll
    for (int i = 0; i < 4; ++i)
#pragma unroll
        for (int j = 0; j < 4; ++j)
#pragma unroll
            for (int k = 0; k < 4; ++k) acc[i][j][k] = 0.f;

    const int arow = lane & 15;
    const int akb  = (lane & 16) ? 16 : 0;
    const int brow = ((lane & 16) ? 8 : 0) + (lane & 7);
    const int bkb  = (lane & 8) ? 16 : 0;

    const uint32_t aHiL = sbase + (wm * 64 + arow) * STRB + akb;
    const uint32_t aLoL = aHiL + TILEB;
    const uint32_t bHiL = sbase + 2 * TILEB + (wn * 32 + brow) * STRB + bkb;

    const int nchunk = K / TKC;

#define GEMM_ISSUE(CHUNK, STAGE)                                              \
    {                                                                         \
        const int k0_ = (CHUNK) * TKC;                                        \
        const uint32_t sb_ = sbase + (STAGE) * STAGEB;                        \
        _Pragma("unroll")                                                     \
        for (int l = 0; l < 4; ++l) {                                         \
            int row = lrowA[l];                                               \
            uint32_t so = row * STRB + lc16 * 16;                             \
            size_t ga = (size_t)(m0 + row) * K + k0_ + lc16 * 8;              \
            size_t gb = (size_t)(n0 + row) * K + k0_ + lc16 * 8;              \
            cp16(sb_ + so, Ahi + ga);                                         \
            cp16(sb_ + TILEB + so, Alo + ga);                                 \
            cp16(sb_ + 2 * TILEB + so, Bhi + gb);                             \
        }                                                                     \
    }

    GEMM_ISSUE(0, 0);
    CP_COMMIT();

    for (int c = 0; c < nchunk; ++c) {
        if (c + 1 < nchunk) {
            GEMM_ISSUE(c + 1, (c + 1) & 1);
            CP_COMMIT();
            CP_WAIT1();
        } else {
            CP_WAIT0();
        }
        __syncthreads();

        const uint32_t stoff = (uint32_t)(c & 1) * STAGEB;
#pragma unroll
        for (int ks = 0; ks < 4; ++ks) {
            uint32_t ah[4][4], al[4][4], bh[2][4];
            // hi A-frags + B-frags first, then hi-MMAs overlap lo ldsm
#pragma unroll
            for (int mt = 0; mt < 4; ++mt)
                ldsm4(ah[mt], aHiL + stoff + mt * (16 * STRB) + ks * 32);
#pragma unroll
            for (int np = 0; np < 2; ++np)
                ldsm4(bh[np], bHiL + stoff + np * (16 * STRB) + ks * 32);
#pragma unroll
            for (int mt = 0; mt < 2; ++mt)
#pragma unroll
                for (int nt = 0; nt < 4; ++nt)
                    mma16816f(acc[mt][nt], ah[mt],
                              bh[nt >> 1][(nt & 1) * 2], bh[nt >> 1][(nt & 1) * 2 + 1]);
#pragma unroll
            for (int mt = 0; mt < 4; ++mt)
                ldsm4(al[mt], aLoL + stoff + mt * (16 * STRB) + ks * 32);
#pragma unroll
            for (int mt = 2; mt < 4; ++mt)
#pragma unroll
                for (int nt = 0; nt < 4; ++nt)
                    mma16816f(acc[mt][nt], ah[mt],
                              bh[nt >> 1][(nt & 1) * 2], bh[nt >> 1][(nt & 1) * 2 + 1]);
#pragma unroll
            for (int mt = 0; mt < 4; ++mt)
#pragma unroll
                for (int nt = 0; nt < 4; ++nt)
                    mma16816f(acc[mt][nt], al[mt],
                              bh[nt >> 1][(nt & 1) * 2], bh[nt >> 1][(nt & 1) * 2 + 1]);
        }
        __syncthreads();
    }
#undef GEMM_ISSUE

    // Epilogue
    const int rbase = m0 + wm * 64 + (lane >> 2);
    const int cbase = n0 + wn * 32 + (lane & 3) * 2;
    if (Cf) {
#pragma unroll
        for (int mt = 0; mt < 4; ++mt) {
#pragma unroll
            for (int nt = 0; nt < 4; ++nt) {
                int r = rbase + mt * 16;
                int col = cbase + nt * 8;
                float2 bv = *reinterpret_cast<const float2*>(bias + col);
                float2 v0, v1;
                v0.x = acc[mt][nt][0] + bv.x;
                v0.y = acc[mt][nt][1] + bv.y;
                v1.x = acc[mt][nt][2] + bv.x;
                v1.y = acc[mt][nt][3] + bv.y;
                *reinterpret_cast<float2*>(Cf + (size_t)r * N + col) = v0;
                *reinterpret_cast<float2*>(Cf + (size_t)(r + 8) * N + col) = v1;
            }
        }
    } else {
#pragma unroll
        for (int mt = 0; mt < 4; ++mt) {
#pragma unroll
            for (int nt = 0; nt < 4; ++nt) {
                int r = rbase + mt * 16;
                int col = cbase + nt * 8;
                float2 bv = *reinterpret_cast<const float2*>(bias + col);
                float v[4];
                v[0] = acc[mt][nt][0] + bv.x;
                v[1] = acc[mt][nt][1] + bv.y;
                v[2] = acc[mt][nt][2] + bv.x;
                v[3] = acc[mt][nt][3] + bv.y;
                __half h0 = __float2half_rn(v[0]);
                __half h1 = __float2half_rn(v[1]);
                __half h2 = __float2half_rn(v[2]);
                __half h3 = __float2half_rn(v[3]);
                uint32_t hp0 = (uint32_t)__half_as_ushort(h0) |
                               ((uint32_t)__half_as_ushort(h1) << 16);
                uint32_t hp1 = (uint32_t)__half_as_ushort(h2) |
                               ((uint32_t)__half_as_ushort(h3) << 16);
                uint32_t lp0 = pack_f16x2(v[0] - __half2float(h0),
                                          v[1] - __half2float(h1));
                uint32_t lp1 = pack_f16x2(v[2] - __half2float(h2),
                                          v[3] - __half2float(h3));
                *reinterpret_cast<uint32_t*>(Chi + (size_t)r * N + col) = hp0;
                *reinterpret_cast<uint32_t*>(Chi + (size_t)(r + 8) * N + col) = hp1;
                *reinterpret_cast<uint32_t*>(Clo + (size_t)r * N + col) = lp0;
                *reinterpret_cast<uint32_t*>(Clo + (size_t)(r + 8) * N + col) = lp1;
            }
        }
    }
}

// ---------------------------------------------------------------------------
// Tensor-core flash attention (fp16 2-term), causal, muP scale 1/DHEAD.
// S = qh*(kh+kl); O += ph*(vh+vl). 128 threads = 4 warps; warp owns 16 rows.
// BM=64, BN=64, D=128. Reads qkv hi/lo fp16; writes y hi/lo fp16.
// ---------------------------------------------------------------------------
#define ASTR 272                 // smem row stride bytes (128 fp16 + 16 pad)
#define ATILE (64 * ASTR)        // 17408 bytes per tile
#define FSM_QH 0
#define FSM_KH (1 * ATILE)
#define FSM_KL (2 * ATILE)
#define FSM_VH (3 * ATILE)
#define FSM_VL (4 * ATILE)
#define FSMEM  (5 * ATILE)       // 87040

__global__ __launch_bounds__(128, 2)
void flash_mma_kernel(const __half* __restrict__ qkvh,
                      const __half* __restrict__ qkvl,
                      __half* __restrict__ yh,
                      __half* __restrict__ yl)
{
    extern __shared__ char sm[];
    const uint32_t sbase = smem_u32(sm);
    const int tid = threadIdx.x;
    const int w = tid >> 5;
    const int lane = tid & 31;

    const int qtile = blockIdx.x;
    const int bh = blockIdx.y;
    const int b = bh >> 4;
    const int h = bh & 15;
    const int q0 = qtile * 64;

    // Q hi only
#pragma unroll
    for (int l = 0; l < 8; ++l) {
        int f = tid + l * 128;
        int row = f >> 4;
        int c8 = f & 15;
        size_t g = (size_t)(b * SEQ + q0 + row) * QKVDIM + h * DHEAD + c8 * 8;
        uint32_t so = row * ASTR + c8 * 16;
        *reinterpret_cast<uint4*>(sm + FSM_QH + so) =
            *reinterpret_cast<const uint4*>(qkvh + g);
    }

    float o[16][4];
#pragma unroll
    for (int i = 0; i < 16; ++i)
#pragma unroll
        for (int j = 0; j < 4; ++j) o[i][j] = 0.f;
    float mrow[2] = {-CUDART_INF_F, -CUDART_INF_F};
    float lrow[2] = {0.f, 0.f};

    const uint32_t qLaneH = sbase + FSM_QH + (w * 16 + (lane & 15)) * ASTR +
                            ((lane & 16) ? 16 : 0);
    const uint32_t kLaneH = sbase + FSM_KH +
                            (((lane & 16) ? 8 : 0) + (lane & 7)) * ASTR +
                            ((lane & 8) ? 16 : 0);
    const uint32_t kLaneL = kLaneH + (FSM_KL - FSM_KH);
    const uint32_t vLaneH = sbase + FSM_VH + (lane & 15) * ASTR +
                            ((lane & 16) ? 16 : 0);
    const uint32_t vLaneL = vLaneH + (FSM_VL - FSM_VH);

    const float SCALE_LOG2E = (1.0f / (float)DHEAD) * 1.44269504088896f;

    for (int kt = 0; kt <= qtile; ++kt) {
        const int k0 = kt * 64;
        __syncthreads();
#pragma unroll
        for (int l = 0; l < 8; ++l) {
            int f = tid + l * 128;
            int row = f >> 4;
            int c8 = f & 15;
            size_t g = (size_t)(b * SEQ + k0 + row) * QKVDIM + h * DHEAD + c8 * 8;
            uint32_t so = row * ASTR + c8 * 16;
            *reinterpret_cast<uint4*>(sm + FSM_KH + so) =
                *reinterpret_cast<const uint4*>(qkvh + DMODEL + g);
            *reinterpret_cast<uint4*>(sm + FSM_KL + so) =
                *reinterpret_cast<const uint4*>(qkvl + DMODEL + g);
            *reinterpret_cast<uint4*>(sm + FSM_VH + so) =
                *reinterpret_cast<const uint4*>(qkvh + 2 * DMODEL + g);
            *reinterpret_cast<uint4*>(sm + FSM_VL + so) =
                *reinterpret_cast<const uint4*>(qkvl + 2 * DMODEL + g);
        }
        __syncthreads();

        // ---- S = qh*(kh + kl) ----
        float sacc[8][4];
#pragma unroll
        for (int i = 0; i < 8; ++i)
#pragma unroll
            for (int j = 0; j < 4; ++j) sacc[i][j] = 0.f;

#pragma unroll
        for (int ks = 0; ks < 8; ++ks) {
            uint32_t ah[4];
            ldsm4(ah, qLaneH + ks * 32);
#pragma unroll
            for (int g = 0; g < 4; ++g) {
                uint32_t bhf[4], blf[4];
                ldsm4(bhf, kLaneH + g * (16 * ASTR) + ks * 32);
                ldsm4(blf, kLaneL + g * (16 * ASTR) + ks * 32);
                mma16816f(sacc[2 * g],     ah, bhf[0], bhf[1]);
                mma16816f(sacc[2 * g + 1], ah, bhf[2], bhf[3]);
                mma16816f(sacc[2 * g],     ah, blf[0], blf[1]);
                mma16816f(sacc[2 * g + 1], ah, blf[2], blf[3]);
            }
        }

        if (kt == qtile) {
            const int rA = w * 16 + (lane >> 2);
#pragma unroll
            for (int nt = 0; nt < 8; ++nt) {
#pragma unroll
                for (int e = 0; e < 4; ++e) {
                    int col = nt * 8 + (lane & 3) * 2 + (e & 1);
                    int row = rA + ((e & 2) ? 8 : 0);
                    if (col > row) sacc[nt][e] = -CUDART_INF_F;
                }
            }
        }

        // ---- online softmax ----
        float mx0 = -CUDART_INF_F, mx1 = -CUDART_INF_F;
#pragma unroll
        for (int nt = 0; nt < 8; ++nt) {
            mx0 = fmaxf(mx0, fmaxf(sacc[nt][0], sacc[nt][1]));
            mx1 = fmaxf(mx1, fmaxf(sacc[nt][2], sacc[nt][3]));
        }
        mx0 = fmaxf(mx0, __shfl_xor_sync(0xffffffffu, mx0, 1));
        mx0 = fmaxf(mx0, __shfl_xor_sync(0xffffffffu, mx0, 2));
        mx1 = fmaxf(mx1, __shfl_xor_sync(0xffffffffu, mx1, 1));
        mx1 = fmaxf(mx1, __shfl_xor_sync(0xffffffffu, mx1, 2));
        float mn0 = fmaxf(mrow[0], mx0 * SCALE_LOG2E);
        float mn1 = fmaxf(mrow[1], mx1 * SCALE_LOG2E);
        float alpha0 = exp2f(mrow[0] - mn0);
        float alpha1 = exp2f(mrow[1] - mn1);
        mrow[0] = mn0; mrow[1] = mn1;

        float sum0 = 0.f, sum1 = 0.f;
#pragma unroll
        for (int nt = 0; nt < 8; ++nt) {
            float p0 = exp2f(sacc[nt][0] * SCALE_LOG2E - mn0);
            float p1 = exp2f(sacc[nt][1] * SCALE_LOG2E - mn0);
            float p2 = exp2f(sacc[nt][2] * SCALE_LOG2E - mn1);
            float p3 = exp2f(sacc[nt][3] * SCALE_LOG2E - mn1);
            sacc[nt][0] = p0; sacc[nt][1] = p1;
            sacc[nt][2] = p2; sacc[nt][3] = p3;
            sum0 += p0 + p1;
            sum1 += p2 + p3;
        }
        sum0 += __shfl_xor_sync(0xffffffffu, sum0, 1);
        sum0 += __shfl_xor_sync(0xffffffffu, sum0, 2);
        sum1 += __shfl_xor_sync(0xffffffffu, sum1, 1);
        sum1 += __shfl_xor_sync(0xffffffffu, sum1, 2);
        lrow[0] = alpha0 * lrow[0] + sum0;
        lrow[1] = alpha1 * lrow[1] + sum1;

#pragma unroll
        for (int nt = 0; nt < 16; ++nt) {
            o[nt][0] *= alpha0; o[nt][1] *= alpha0;
            o[nt][2] *= alpha1; o[nt][3] *= alpha1;
        }

        // ---- O += ph*(vh + vl) ----
#pragma unroll
        for (int kc = 0; kc < 4; ++kc) {
            uint32_t pa_h[4];
#pragma unroll
            for (int half = 0; half < 2; ++half) {
                const float* s2 = sacc[2 * kc + half];
#pragma unroll
                for (int rr = 0; rr < 2; ++rr) {
                    pa_h[half * 2 + rr] = pack_f16x2(s2[rr * 2 + 0], s2[rr * 2 + 1]);
                }
            }
#pragma unroll
            for (int ng = 0; ng < 8; ++ng) {
                uint32_t vh[4], vl[4];
                ldsm4t(vh, vLaneH + kc * (16 * ASTR) + ng * 32);
                ldsm4t(vl, vLaneL + kc * (16 * ASTR) + ng * 32);
                mma16816f(o[2 * ng],     pa_h, vh[0], vh[1]);
                mma16816f(o[2 * ng + 1], pa_h, vh[2], vh[3]);
                mma16816f(o[2 * ng],     pa_h, vl[0], vl[1]);
                mma16816f(o[2 * ng + 1], pa_h, vl[2], vl[3]);
            }
        }
    }

    // ---- epilogue ----
    const float inv0 = 1.0f / lrow[0];
    const float inv1 = 1.0f / lrow[1];
    const int rowA = q0 + w * 16 + (lane >> 2);
#pragma unroll
    for (int nt = 0; nt < 16; ++nt) {
        int col = h * DHEAD + nt * 8 + (lane & 3) * 2;
        float v0 = o[nt][0] * inv0, v1 = o[nt][1] * inv0;
        float v2 = o[nt][2] * inv1, v3 = o[nt][3] * inv1;
        __half h0 = __float2half_rn(v0);
        __half h1 = __float2half_rn(v1);
        __half h2 = __float2half_rn(v2);
        __half h3 = __float2half_rn(v3);
        uint32_t hp0 = (uint32_t)__half_as_ushort(h0) |
                       ((uint32_t)__half_as_ushort(h1) << 16);
        uint32_t hp1 = (uint32_t)__half_as_ushort(h2) |
                       ((uint32_t)__half_as_ushort(h3) << 16);
        uint32_t lp0 = pack_f16x2(v0 - __half2float(h0),
                                  v1 - __half2float(h1));
        uint32_t lp1 = pack_f16x2(v2 - __half2float(h2),
                                  v3 - __half2float(h3));
        size_t r0 = (size_t)(b * SEQ + rowA) * DMODEL + col;
        size_t r1 = (size_t)(b * SEQ + rowA + 8) * DMODEL + col;
        *reinterpret_cast<uint32_t*>(yh + r0) = hp0;
        *reinterpret_cast<uint32_t*>(yh + r1) = hp1;
        *reinterpret_cast<uint32_t*>(yl + r0) = lp0;
        *reinterpret_cast<uint32_t*>(yl + r1) = lp1;
    }
}

// ---------------------------------------------------------------------------
// Launch
// ---------------------------------------------------------------------------
extern "C" void kernel_launch(void* const* d_in, const int* in_sizes, int n_in,
                              void* d_out, int out_size)
{
    const float* x     = (const float*)d_in[0];
    const float* W_qkv = (const float*)d_in[1];
    const float* b_qkv = (const float*)d_in[2];
    const float* W_out = (const float*)d_in[3];
    const float* b_out = (const float*)d_in[4];
    float* out = (float*)d_out;

    void *p_xh, *p_xl, *p_wqh, *p_woh, *p_qh, *p_ql, *p_yh, *p_yl;
    cudaGetSymbolAddress(&p_xh, g_x_hi);
    cudaGetSymbolAddress(&p_xl, g_x_lo);
    cudaGetSymbolAddress(&p_wqh, g_wqkv_hi);
    cudaGetSymbolAddress(&p_woh, g_wout_hi);
    cudaGetSymbolAddress(&p_qh, g_qkv_hi);
    cudaGetSymbolAddress(&p_ql, g_qkv_lo);
    cudaGetSymbolAddress(&p_yh, g_y_hi);
    cudaGetSymbolAddress(&p_yl, g_y_lo);

    cudaFuncSetAttribute(gemm_mma_kernel,
                         cudaFuncAttributeMaxDynamicSharedMemorySize, GSMEM);
    cudaFuncSetAttribute(flash_mma_kernel,
                         cudaFuncAttributeMaxDynamicSharedMemorySize, FSMEM);

    // 0) Splits
    {
        int n4 = NTOK * DMODEL / 4;
        split_kernel<<<(n4 + 255) / 256, 256>>>(x, (__half*)p_xh, (__half*)p_xl, n4);
        dim3 blk(32, 8);
        transpose_cvt_kernel<<<dim3(QKVDIM / 32, DMODEL / 32), blk>>>(
            W_qkv, (__half*)p_wqh, DMODEL, QKVDIM);
        transpose_cvt_kernel<<<dim3(DMODEL / 32, DMODEL / 32), blk>>>(
            W_out, (__half*)p_woh, DMODEL, DMODEL);
    }

    // 1) QKV projection -> qkv hi/lo fp16 (split epilogue)
    gemm_mma_kernel<<<dim3(QKVDIM / TBN, NTOK / TBM), 256, GSMEM>>>(
        (const __half*)p_xh, (const __half*)p_xl, (const __half*)p_wqh,
        b_qkv, nullptr,
        (__half*)p_qh, (__half*)p_ql,
        NTOK, QKVDIM, DMODEL);

    // 2) Attention (tensor-core flash, fp16 2-term) -> y hi/lo fp16
    flash_mma_kernel<<<dim3(SEQ / 64, BATCH * NHEADS), 128, FSMEM>>>(
        (const __half*)p_qh, (const __half*)p_ql,
        (__half*)p_yh, (__half*)p_yl);

    // 3) Output projection -> fp32 out
    gemm_mma_kernel<<<dim3(DMODEL / TBN, NTOK / TBM), 256, GSMEM>>>(
        (const __half*)p_yh, (const __half*)p_yl, (const __half*)p_woh,
        b_out, out, nullptr, nullptr,
        NTOK, DMODEL, DMODEL);
}

// round 8
// speedup vs baseline: 5.1781x; 1.0448x over previous
#include <cuda_runtime.h>
#include <cuda_fp16.h>
#include <math_constants.h>
#include <cstdint>

// Problem constants
#define BATCH   4
#define SEQ     2048
#define DMODEL  2048
#define NHEADS  16
#define DHEAD   128
#define QKVDIM  (3 * DMODEL)       // 6144
#define NTOK    (BATCH * SEQ)      // 8192

// ---------------------------------------------------------------------------
// Scratch (__device__ globals; no cudaMalloc allowed)
// ---------------------------------------------------------------------------
__device__ __half g_x_hi[(size_t)NTOK * DMODEL];
__device__ __half g_wqkv_hi[(size_t)QKVDIM * DMODEL];  // transposed [N,K]
__device__ __half g_wout_hi[(size_t)DMODEL * DMODEL];  // transposed [N,K]
__device__ __half g_qkv_hi[(size_t)NTOK * QKVDIM];
__device__ __half g_y_hi[(size_t)NTOK * DMODEL];
__device__ __half g_y_lo[(size_t)NTOK * DMODEL];

// ---------------------------------------------------------------------------
// Warp-MMA / async-copy helpers (plain PTX, compute_103-safe)
// ---------------------------------------------------------------------------
__device__ __forceinline__ uint32_t smem_u32(const void* p) {
    uint32_t a;
    asm("{ .reg .u64 t; cvta.to.shared.u64 t, %1; cvt.u32.u64 %0, t; }"
        : "=r"(a) : "l"(p));
    return a;
}

__device__ __forceinline__ void ldsm4(uint32_t r[4], uint32_t addr) {
    asm volatile("ldmatrix.sync.aligned.m8n8.x4.shared.b16 {%0,%1,%2,%3}, [%4];"
                 : "=r"(r[0]), "=r"(r[1]), "=r"(r[2]), "=r"(r[3]) : "r"(addr));
}
__device__ __forceinline__ void ldsm4t(uint32_t r[4], uint32_t addr) {
    asm volatile("ldmatrix.sync.aligned.m8n8.x4.trans.shared.b16 {%0,%1,%2,%3}, [%4];"
                 : "=r"(r[0]), "=r"(r[1]), "=r"(r[2]), "=r"(r[3]) : "r"(addr));
}

__device__ __forceinline__ void mma16816f(float c[4], const uint32_t a[4],
                                          uint32_t b0, uint32_t b1) {
    asm volatile(
        "mma.sync.aligned.m16n8k16.row.col.f32.f16.f16.f32 "
        "{%0,%1,%2,%3}, {%4,%5,%6,%7}, {%8,%9}, {%0,%1,%2,%3};"
        : "+f"(c[0]), "+f"(c[1]), "+f"(c[2]), "+f"(c[3])
        : "r"(a[0]), "r"(a[1]), "r"(a[2]), "r"(a[3]), "r"(b0), "r"(b1));
}

// pack two fp32 -> f16x2 (first arg in bits [0,16))
__device__ __forceinline__ uint32_t pack_f16x2(float lo, float hi) {
    uint32_t r;
    asm("cvt.rn.f16x2.f32 %0, %1, %2;" : "=r"(r) : "f"(hi), "f"(lo));
    return r;
}

__device__ __forceinline__ void cp16(uint32_t dst, const void* src) {
    asm volatile("cp.async.cg.shared.global [%0], [%1], 16;"
                 :: "r"(dst), "l"(src));
}
#define CP_COMMIT() asm volatile("cp.async.commit_group;" ::: "memory")
#define CP_WAIT0()  asm volatile("cp.async.wait_group 0;" ::: "memory")
#define CP_WAIT1()  asm volatile("cp.async.wait_group 1;" ::: "memory")

// ---------------------------------------------------------------------------
// Convert kernels
// ---------------------------------------------------------------------------
// fp32 -> fp16 (hi only)
__global__ void cvt_kernel(const float* __restrict__ in,
                           __half* __restrict__ hi, int n4)
{
    int i = blockIdx.x * blockDim.x + threadIdx.x;
    if (i >= n4) return;
    float4 v = reinterpret_cast<const float4*>(in)[i];
    unsigned short hraw[4];
    hraw[0] = __half_as_ushort(__float2half_rn(v.x));
    hraw[1] = __half_as_ushort(__float2half_rn(v.y));
    hraw[2] = __half_as_ushort(__float2half_rn(v.z));
    hraw[3] = __half_as_ushort(__float2half_rn(v.w));
    reinterpret_cast<uint64_t*>(hi)[i] = *reinterpret_cast<uint64_t*>(hraw);
}

// W [K,N] fp32 -> Thi [N,K] fp16 (transpose + round; hi only)
__global__ void transpose_cvt_kernel(const float* __restrict__ W,
                                     __half* __restrict__ Thi,
                                     int K, int N)
{
    __shared__ float tile[32][33];
    int nx = blockIdx.x * 32 + threadIdx.x;
    int k0 = blockIdx.y * 32;
#pragma unroll
    for (int j = 0; j < 32; j += 8)
        tile[threadIdx.y + j][threadIdx.x] = W[(size_t)(k0 + threadIdx.y + j) * N + nx];
    __syncthreads();
    int k = k0 + threadIdx.x;
    int nbase = blockIdx.x * 32 + threadIdx.y;
#pragma unroll
    for (int j = 0; j < 32; j += 8)
        Thi[(size_t)(nbase + j) * K + k] = __float2half_rn(tile[threadIdx.x][threadIdx.y + j]);
}

// ---------------------------------------------------------------------------
// fp16 GEMM via warp mma.sync with cp.async double buffering:
//   C[M,N] = (Ahi [+ Alo])[M,K] @ Bhi[N,K]^T + bias
// Alo == nullptr -> 1-term. CTA 128x128, 8 warps, warp tile 64x32, K-chunk 64.
// Epilogue: fp32 (Cf) OR fp16 hi (Chi, Clo=null) OR fp16 hi/lo split.
// ---------------------------------------------------------------------------
#define TBM 128
#define TBN 128
#define TKC 64
#define STRB 144                 // smem row stride bytes (64 fp16 + 16 pad)
#define TILEB (128 * STRB)       // 18432
#define STAGEB (3 * TILEB)       // 55296: [Ahi][Alo][Bhi]
#define GSMEM (2 * STAGEB)       // 110592

__global__ __launch_bounds__(256, 2)
void gemm_mma_kernel(const __half* __restrict__ Ahi,
                     const __half* __restrict__ Alo,
                     const __half* __restrict__ Bhi,
                     const float* __restrict__ bias,
                     float* __restrict__ Cf,
                     __half* __restrict__ Chi,
                     __half* __restrict__ Clo,
                     int M, int N, int K)
{
    extern __shared__ char sm[];
    const uint32_t sbase = smem_u32(sm);
    const int tid = threadIdx.x;
    const int wid = tid >> 5;
    const int lane = tid & 31;
    const int m0 = blockIdx.y * TBM;
    const int n0 = blockIdx.x * TBN;
    const int wm = wid & 1;
    const int wn = wid >> 1;

    const int lrowA[4] = { (tid + 0) >> 3, (tid + 256) >> 3,
                           (tid + 512) >> 3, (tid + 768) >> 3 };
    const int lc16 = tid & 7;

    float acc[4][4][4];
#pragma unroll
    for (int i = 0; i < 4; ++i)
#pragma unroll
        for (int j = 0; j < 4; ++j)
#pragma unroll
            for (int k = 0; k < 4; ++k) acc[i][j][k] = 0.f;

    const int arow = lane & 15;
    const int akb  = (lane & 16) ? 16 : 0;
    const int brow = ((lane & 16) ? 8 : 0) + (lane & 7);
    const int bkb  = (lane & 8) ? 16 : 0;

    const uint32_t aHiL = sbase + (wm * 64 + arow) * STRB + akb;
    const uint32_t aLoL = aHiL + TILEB;
    const uint32_t bHiL = sbase + 2 * TILEB + (wn * 32 + brow) * STRB + bkb;

    const int nchunk = K / TKC;

#define GEMM_ISSUE(CHUNK, STAGE)                                              \
    {                                                                         \
        const int k0_ = (CHUNK) * TKC;                                        \
        const uint32_t sb_ = sbase + (STAGE) * STAGEB;                        \
        _Pragma("unroll")                                                     \
        for (int l = 0; l < 4; ++l) {                                         \
            int row = lrowA[l];                                               \
            uint32_t so = row * STRB + lc16 * 16;                             \
            size_t ga = (size_t)(m0 + row) * K + k0_ + lc16 * 8;              \
            size_t gb = (size_t)(n0 + row) * K + k0_ + lc16 * 8;              \
            cp16(sb_ + so, Ahi + ga);                                         \
            if (Alo) cp16(sb_ + TILEB + so, Alo + ga);                        \
            cp16(sb_ + 2 * TILEB + so, Bhi + gb);                             \
        }                                                                     \
    }

    GEMM_ISSUE(0, 0);
    CP_COMMIT();

    for (int c = 0; c < nchunk; ++c) {
        if (c + 1 < nchunk) {
            GEMM_ISSUE(c + 1, (c + 1) & 1);
            CP_COMMIT();
            CP_WAIT1();
        } else {
            CP_WAIT0();
        }
        __syncthreads();

        const uint32_t stoff = (uint32_t)(c & 1) * STAGEB;
#pragma unroll
        for (int ks = 0; ks < 4; ++ks) {
            uint32_t ah[4][4], bh[2][4];
#pragma unroll
            for (int mt = 0; mt < 4; ++mt)
                ldsm4(ah[mt], aHiL + stoff + mt * (16 * STRB) + ks * 32);
#pragma unroll
            for (int np = 0; np < 2; ++np)
                ldsm4(bh[np], bHiL + stoff + np * (16 * STRB) + ks * 32);
#pragma unroll
            for (int mt = 0; mt < 4; ++mt)
#pragma unroll
                for (int nt = 0; nt < 4; ++nt)
                    mma16816f(acc[mt][nt], ah[mt],
                              bh[nt >> 1][(nt & 1) * 2], bh[nt >> 1][(nt & 1) * 2 + 1]);
            if (Alo) {
                uint32_t al[4][4];
#pragma unroll
                for (int mt = 0; mt < 4; ++mt)
                    ldsm4(al[mt], aLoL + stoff + mt * (16 * STRB) + ks * 32);
#pragma unroll
                for (int mt = 0; mt < 4; ++mt)
#pragma unroll
                    for (int nt = 0; nt < 4; ++nt)
                        mma16816f(acc[mt][nt], al[mt],
                                  bh[nt >> 1][(nt & 1) * 2], bh[nt >> 1][(nt & 1) * 2 + 1]);
            }
        }
        __syncthreads();
    }
#undef GEMM_ISSUE

    // Epilogue
    const int rbase = m0 + wm * 64 + (lane >> 2);
    const int cbase = n0 + wn * 32 + (lane & 3) * 2;
    if (Cf) {
#pragma unroll
        for (int mt = 0; mt < 4; ++mt) {
#pragma unroll
            for (int nt = 0; nt < 4; ++nt) {
                int r = rbase + mt * 16;
                int col = cbase + nt * 8;
                float2 bv = *reinterpret_cast<const float2*>(bias + col);
                float2 v0, v1;
                v0.x = acc[mt][nt][0] + bv.x;
                v0.y = acc[mt][nt][1] + bv.y;
                v1.x = acc[mt][nt][2] + bv.x;
                v1.y = acc[mt][nt][3] + bv.y;
                *reinterpret_cast<float2*>(Cf + (size_t)r * N + col) = v0;
                *reinterpret_cast<float2*>(Cf + (size_t)(r + 8) * N + col) = v1;
            }
        }
    } else if (Clo) {
#pragma unroll
        for (int mt = 0; mt < 4; ++mt) {
#pragma unroll
            for (int nt = 0; nt < 4; ++nt) {
                int r = rbase + mt * 16;
                int col = cbase + nt * 8;
                float2 bv = *reinterpret_cast<const float2*>(bias + col);
                float v[4];
                v[0] = acc[mt][nt][0] + bv.x;
                v[1] = acc[mt][nt][1] + bv.y;
                v[2] = acc[mt][nt][2] + bv.x;
                v[3] = acc[mt][nt][3] + bv.y;
                __half h0 = __float2half_rn(v[0]);
                __half h1 = __float2half_rn(v[1]);
                __half h2 = __float2half_rn(v[2]);
                __half h3 = __float2half_rn(v[3]);
                uint32_t hp0 = (uint32_t)__half_as_ushort(h0) |
                               ((uint32_t)__half_as_ushort(h1) << 16);
                uint32_t hp1 = (uint32_t)__half_as_ushort(h2) |
                               ((uint32_t)__half_as_ushort(h3) << 16);
                uint32_t lp0 = pack_f16x2(v[0] - __half2float(h0),
                                          v[1] - __half2float(h1));
                uint32_t lp1 = pack_f16x2(v[2] - __half2float(h2),
                                          v[3] - __half2float(h3));
                *reinterpret_cast<uint32_t*>(Chi + (size_t)r * N + col) = hp0;
                *reinterpret_cast<uint32_t*>(Chi + (size_t)(r + 8) * N + col) = hp1;
                *reinterpret_cast<uint32_t*>(Clo + (size_t)r * N + col) = lp0;
                *reinterpret_cast<uint32_t*>(Clo + (size_t)(r + 8) * N + col) = lp1;
            }
        }
    } else {
        // hi-only fp16 epilogue
#pragma unroll
        for (int mt = 0; mt < 4; ++mt) {
#pragma unroll
            for (int nt = 0; nt < 4; ++nt) {
                int r = rbase + mt * 16;
                int col = cbase + nt * 8;
                float2 bv = *reinterpret_cast<const float2*>(bias + col);
                uint32_t hp0 = pack_f16x2(acc[mt][nt][0] + bv.x,
                                          acc[mt][nt][1] + bv.y);
                uint32_t hp1 = pack_f16x2(acc[mt][nt][2] + bv.x,
                                          acc[mt][nt][3] + bv.y);
                *reinterpret_cast<uint32_t*>(Chi + (size_t)r * N + col) = hp0;
                *reinterpret_cast<uint32_t*>(Chi + (size_t)(r + 8) * N + col) = hp1;
            }
        }
    }
}

// ---------------------------------------------------------------------------
// Tensor-core flash attention (pure fp16 inputs, fp32 accum), causal,
// muP scale 1/DHEAD. 128 threads = 4 warps; warp owns 16 query rows.
// BM=64, BN=64, D=128. Reads qkv hi fp16; writes y hi/lo fp16 split.
// ---------------------------------------------------------------------------
#define ASTR 272                 // smem row stride bytes (128 fp16 + 16 pad)
#define ATILE (64 * ASTR)        // 17408 bytes per tile
#define FSM_QH 0
#define FSM_KH (1 * ATILE)
#define FSM_VH (2 * ATILE)
#define FSMEM  (3 * ATILE)       // 52224

__global__ __launch_bounds__(128, 3)
void flash_mma_kernel(const __half* __restrict__ qkvh,
                      __half* __restrict__ yh,
                      __half* __restrict__ yl)
{
    extern __shared__ char sm[];
    const uint32_t sbase = smem_u32(sm);
    const int tid = threadIdx.x;
    const int w = tid >> 5;
    const int lane = tid & 31;

    const int qtile = blockIdx.x;
    const int bh = blockIdx.y;
    const int b = bh >> 4;
    const int h = bh & 15;
    const int q0 = qtile * 64;

#pragma unroll
    for (int l = 0; l < 8; ++l) {
        int f = tid + l * 128;
        int row = f >> 4;
        int c8 = f & 15;
        size_t g = (size_t)(b * SEQ + q0 + row) * QKVDIM + h * DHEAD + c8 * 8;
        uint32_t so = row * ASTR + c8 * 16;
        *reinterpret_cast<uint4*>(sm + FSM_QH + so) =
            *reinterpret_cast<const uint4*>(qkvh + g);
    }

    float o[16][4];
#pragma unroll
    for (int i = 0; i < 16; ++i)
#pragma unroll
        for (int j = 0; j < 4; ++j) o[i][j] = 0.f;
    float mrow[2] = {-CUDART_INF_F, -CUDART_INF_F};
    float lrow[2] = {0.f, 0.f};

    const uint32_t qLaneH = sbase + FSM_QH + (w * 16 + (lane & 15)) * ASTR +
                            ((lane & 16) ? 16 : 0);
    const uint32_t kLaneH = sbase + FSM_KH +
                            (((lane & 16) ? 8 : 0) + (lane & 7)) * ASTR +
                            ((lane & 8) ? 16 : 0);
    const uint32_t vLaneH = sbase + FSM_VH + (lane & 15) * ASTR +
                            ((lane & 16) ? 16 : 0);

    const float SCALE_LOG2E = (1.0f / (float)DHEAD) * 1.44269504088896f;

    for (int kt = 0; kt <= qtile; ++kt) {
        const int k0 = kt * 64;
        __syncthreads();
#pragma unroll
        for (int l = 0; l < 8; ++l) {
            int f = tid + l * 128;
            int row = f >> 4;
            int c8 = f & 15;
            size_t g = (size_t)(b * SEQ + k0 + row) * QKVDIM + h * DHEAD + c8 * 8;
            uint32_t so = row * ASTR + c8 * 16;
            *reinterpret_cast<uint4*>(sm + FSM_KH + so) =
                *reinterpret_cast<const uint4*>(qkvh + DMODEL + g);
            *reinterpret_cast<uint4*>(sm + FSM_VH + so) =
                *reinterpret_cast<const uint4*>(qkvh + 2 * DMODEL + g);
        }
        __syncthreads();

        // ---- S = q * k^T ----
        float sacc[8][4];
#pragma unroll
        for (int i = 0; i < 8; ++i)
#pragma unroll
            for (int j = 0; j < 4; ++j) sacc[i][j] = 0.f;

#pragma unroll
        for (int ks = 0; ks < 8; ++ks) {
            uint32_t ah[4];
            ldsm4(ah, qLaneH + ks * 32);
#pragma unroll
            for (int g = 0; g < 4; ++g) {
                uint32_t bhf[4];
                ldsm4(bhf, kLaneH + g * (16 * ASTR) + ks * 32);
                mma16816f(sacc[2 * g],     ah, bhf[0], bhf[1]);
                mma16816f(sacc[2 * g + 1], ah, bhf[2], bhf[3]);
            }
        }

        if (kt == qtile) {
            const int rA = w * 16 + (lane >> 2);
#pragma unroll
            for (int nt = 0; nt < 8; ++nt) {
#pragma unroll
                for (int e = 0; e < 4; ++e) {
                    int col = nt * 8 + (lane & 3) * 2 + (e & 1);
                    int row = rA + ((e & 2) ? 8 : 0);
                    if (col > row) sacc[nt][e] = -CUDART_INF_F;
                }
            }
        }

        // ---- online softmax ----
        float mx0 = -CUDART_INF_F, mx1 = -CUDART_INF_F;
#pragma unroll
        for (int nt = 0; nt < 8; ++nt) {
            mx0 = fmaxf(mx0, fmaxf(sacc[nt][0], sacc[nt][1]));
            mx1 = fmaxf(mx1, fmaxf(sacc[nt][2], sacc[nt][3]));
        }
        mx0 = fmaxf(mx0, __shfl_xor_sync(0xffffffffu, mx0, 1));
        mx0 = fmaxf(mx0, __shfl_xor_sync(0xffffffffu, mx0, 2));
        mx1 = fmaxf(mx1, __shfl_xor_sync(0xffffffffu, mx1, 1));
        mx1 = fmaxf(mx1, __shfl_xor_sync(0xffffffffu, mx1, 2));
        float mn0 = fmaxf(mrow[0], mx0 * SCALE_LOG2E);
        float mn1 = fmaxf(mrow[1], mx1 * SCALE_LOG2E);
        float alpha0 = exp2f(mrow[0] - mn0);
        float alpha1 = exp2f(mrow[1] - mn1);
        mrow[0] = mn0; mrow[1] = mn1;

        float sum0 = 0.f, sum1 = 0.f;
#pragma unroll
        for (int nt = 0; nt < 8; ++nt) {
            float p0 = exp2f(sacc[nt][0] * SCALE_LOG2E - mn0);
            float p1 = exp2f(sacc[nt][1] * SCALE_LOG2E - mn0);
            float p2 = exp2f(sacc[nt][2] * SCALE_LOG2E - mn1);
            float p3 = exp2f(sacc[nt][3] * SCALE_LOG2E - mn1);
            sacc[nt][0] = p0; sacc[nt][1] = p1;
            sacc[nt][2] = p2; sacc[nt][3] = p3;
            sum0 += p0 + p1;
            sum1 += p2 + p3;
        }
        sum0 += __shfl_xor_sync(0xffffffffu, sum0, 1);
        sum0 += __shfl_xor_sync(0xffffffffu, sum0, 2);
        sum1 += __shfl_xor_sync(0xffffffffu, sum1, 1);
        sum1 += __shfl_xor_sync(0xffffffffu, sum1, 2);
        lrow[0] = alpha0 * lrow[0] + sum0;
        lrow[1] = alpha1 * lrow[1] + sum1;

#pragma unroll
        for (int nt = 0; nt < 16; ++nt) {
            o[nt][0] *= alpha0; o[nt][1] *= alpha0;
            o[nt][2] *= alpha1; o[nt][3] *= alpha1;
        }

        // ---- O += p * v ----
#pragma unroll
        for (int kc = 0; kc < 4; ++kc) {
            uint32_t pa_h[4];
#pragma unroll
            for (int half = 0; half < 2; ++half) {
                const float* s2 = sacc[2 * kc + half];
#pragma unroll
                for (int rr = 0; rr < 2; ++rr) {
                    pa_h[half * 2 + rr] = pack_f16x2(s2[rr * 2 + 0], s2[rr * 2 + 1]);
                }
            }
#pragma unroll
            for (int ng = 0; ng < 8; ++ng) {
                uint32_t vh[4];
                ldsm4t(vh, vLaneH + kc * (16 * ASTR) + ng * 32);
                mma16816f(o[2 * ng],     pa_h, vh[0], vh[1]);
                mma16816f(o[2 * ng + 1], pa_h, vh[2], vh[3]);
            }
        }
    }

    // ---- epilogue: normalize, split hi/lo, write y ----
    const float inv0 = 1.0f / lrow[0];
    const float inv1 = 1.0f / lrow[1];
    const int rowA = q0 + w * 16 + (lane >> 2);
#pragma unroll
    for (int nt = 0; nt < 16; ++nt) {
        int col = h * DHEAD + nt * 8 + (lane & 3) * 2;
        float v0 = o[nt][0] * inv0, v1 = o[nt][1] * inv0;
        float v2 = o[nt][2] * inv1, v3 = o[nt][3] * inv1;
        __half h0 = __float2half_rn(v0);
        __half h1 = __float2half_rn(v1);
        __half h2 = __float2half_rn(v2);
        __half h3 = __float2half_rn(v3);
        uint32_t hp0 = (uint32_t)__half_as_ushort(h0) |
                       ((uint32_t)__half_as_ushort(h1) << 16);
        uint32_t hp1 = (uint32_t)__half_as_ushort(h2) |
                       ((uint32_t)__half_as_ushort(h3) << 16);
        uint32_t lp0 = pack_f16x2(v0 - __half2float(h0),
                                  v1 - __half2float(h1));
        uint32_t lp1 = pack_f16x2(v2 - __half2float(h2),
                                  v3 - __half2float(h3));
        size_t r0 = (size_t)(b * SEQ + rowA) * DMODEL + col;
        size_t r1 = (size_t)(b * SEQ + rowA + 8) * DMODEL + col;
        *reinterpret_cast<uint32_t*>(yh + r0) = hp0;
        *reinterpret_cast<uint32_t*>(yh + r1) = hp1;
        *reinterpret_cast<uint32_t*>(yl + r0) = lp0;
        *reinterpret_cast<uint32_t*>(yl + r1) = lp1;
    }
}

// ---------------------------------------------------------------------------
// Launch
// ---------------------------------------------------------------------------
extern "C" void kernel_launch(void* const* d_in, const int* in_sizes, int n_in,
                              void* d_out, int out_size)
{
    const float* x     = (const float*)d_in[0];
    const float* W_qkv = (const float*)d_in[1];
    const float* b_qkv = (const float*)d_in[2];
    const float* W_out = (const float*)d_in[3];
    const float* b_out = (const float*)d_in[4];
    float* out = (float*)d_out;

    void *p_xh, *p_wqh, *p_woh, *p_qh, *p_yh, *p_yl;
    cudaGetSymbolAddress(&p_xh, g_x_hi);
    cudaGetSymbolAddress(&p_wqh, g_wqkv_hi);
    cudaGetSymbolAddress(&p_woh, g_wout_hi);
    cudaGetSymbolAddress(&p_qh, g_qkv_hi);
    cudaGetSymbolAddress(&p_yh, g_y_hi);
    cudaGetSymbolAddress(&p_yl, g_y_lo);

    cudaFuncSetAttribute(gemm_mma_kernel,
                         cudaFuncAttributeMaxDynamicSharedMemorySize, GSMEM);
    cudaFuncSetAttribute(flash_mma_kernel,
                         cudaFuncAttributeMaxDynamicSharedMemorySize, FSMEM);

    // 0) Converts
    {
        int n4 = NTOK * DMODEL / 4;
        cvt_kernel<<<(n4 + 255) / 256, 256>>>(x, (__half*)p_xh, n4);
        dim3 blk(32, 8);
        transpose_cvt_kernel<<<dim3(QKVDIM / 32, DMODEL / 32), blk>>>(
            W_qkv, (__half*)p_wqh, DMODEL, QKVDIM);
        transpose_cvt_kernel<<<dim3(DMODEL / 32, DMODEL / 32), blk>>>(
            W_out, (__half*)p_woh, DMODEL, DMODEL);
    }

    // 1) QKV projection (pure fp16, 1-term) -> qkv hi fp16
    gemm_mma_kernel<<<dim3(QKVDIM / TBN, NTOK / TBM), 256, GSMEM>>>(
        (const __half*)p_xh, nullptr, (const __half*)p_wqh,
        b_qkv, nullptr,
        (__half*)p_qh, nullptr,
        NTOK, QKVDIM, DMODEL);

    // 2) Attention (pure fp16 flash) -> y hi/lo fp16 split
    flash_mma_kernel<<<dim3(SEQ / 64, BATCH * NHEADS), 128, FSMEM>>>(
        (const __half*)p_qh, (__half*)p_yh, (__half*)p_yl);

    // 3) Output projection (2-term: y hi + y lo) -> fp32 out
    gemm_mma_kernel<<<dim3(DMODEL / TBN, NTOK / TBM), 256, GSMEM>>>(
        (const __half*)p_yh, (const __half*)p_yl, (const __half*)p_woh,
        b_out, out, nullptr, nullptr,
        NTOK, DMODEL, DMODEL);
}

// round 13
// speedup vs baseline: 9.2563x; 1.7876x over previous
#include <cuda_runtime.h>
#include <cuda_fp16.h>
#include <math_constants.h>
#include <cstdint>

// Problem constants
#define BATCH   4
#define SEQ     2048
#define DMODEL  2048
#define NHEADS  16
#define DHEAD   128
#define QKVDIM  (3 * DMODEL)       // 6144
#define NTOK    (BATCH * SEQ)      // 8192

// ---------------------------------------------------------------------------
// Scratch (__device__ globals; no cudaMalloc allowed)
// ---------------------------------------------------------------------------
__device__ __half g_x_hi[(size_t)NTOK * DMODEL];
__device__ __half g_wqkv_hi[(size_t)QKVDIM * DMODEL];  // transposed [N,K]
__device__ __half g_wout_hi[(size_t)DMODEL * DMODEL];  // transposed [N,K]
__device__ __half g_qkv_hi[(size_t)NTOK * QKVDIM];
__device__ __half g_y_hi[(size_t)NTOK * DMODEL];

// ---------------------------------------------------------------------------
// Warp-MMA / async-copy helpers (plain PTX, compute_103-safe)
// ---------------------------------------------------------------------------
__device__ __forceinline__ uint32_t smem_u32(const void* p) {
    uint32_t a;
    asm("{ .reg .u64 t; cvta.to.shared.u64 t, %1; cvt.u32.u64 %0, t; }"
        : "=r"(a) : "l"(p));
    return a;
}

__device__ __forceinline__ void ldsm4(uint32_t r[4], uint32_t addr) {
    asm volatile("ldmatrix.sync.aligned.m8n8.x4.shared.b16 {%0,%1,%2,%3}, [%4];"
                 : "=r"(r[0]), "=r"(r[1]), "=r"(r[2]), "=r"(r[3]) : "r"(addr));
}
__device__ __forceinline__ void ldsm4t(uint32_t r[4], uint32_t addr) {
    asm volatile("ldmatrix.sync.aligned.m8n8.x4.trans.shared.b16 {%0,%1,%2,%3}, [%4];"
                 : "=r"(r[0]), "=r"(r[1]), "=r"(r[2]), "=r"(r[3]) : "r"(addr));
}

__device__ __forceinline__ void mma16816f(float c[4], const uint32_t a[4],
                                          uint32_t b0, uint32_t b1) {
    asm volatile(
        "mma.sync.aligned.m16n8k16.row.col.f32.f16.f16.f32 "
        "{%0,%1,%2,%3}, {%4,%5,%6,%7}, {%8,%9}, {%0,%1,%2,%3};"
        : "+f"(c[0]), "+f"(c[1]), "+f"(c[2]), "+f"(c[3])
        : "r"(a[0]), "r"(a[1]), "r"(a[2]), "r"(a[3]), "r"(b0), "r"(b1));
}

// pack two fp32 -> f16x2 (first arg in bits [0,16))
__device__ __forceinline__ uint32_t pack_f16x2(float lo, float hi) {
    uint32_t r;
    asm("cvt.rn.f16x2.f32 %0, %1, %2;" : "=r"(r) : "f"(hi), "f"(lo));
    return r;
}

__device__ __forceinline__ void cp16(uint32_t dst, const void* src) {
    asm volatile("cp.async.cg.shared.global [%0], [%1], 16;"
                 :: "r"(dst), "l"(src));
}
#define CP_COMMIT() asm volatile("cp.async.commit_group;" ::: "memory")
#define CP_WAIT0()  asm volatile("cp.async.wait_group 0;" ::: "memory")
#define CP_WAIT1()  asm volatile("cp.async.wait_group 1;" ::: "memory")

// ---------------------------------------------------------------------------
// Convert kernels
// ---------------------------------------------------------------------------
__global__ void cvt_kernel(const float* __restrict__ in,
                           __half* __restrict__ hi, int n4)
{
    int i = blockIdx.x * blockDim.x + threadIdx.x;
    if (i >= n4) return;
    float4 v = reinterpret_cast<const float4*>(in)[i];
    unsigned short hraw[4];
    hraw[0] = __half_as_ushort(__float2half_rn(v.x));
    hraw[1] = __half_as_ushort(__float2half_rn(v.y));
    hraw[2] = __half_as_ushort(__float2half_rn(v.z));
    hraw[3] = __half_as_ushort(__float2half_rn(v.w));
    reinterpret_cast<uint64_t*>(hi)[i] = *reinterpret_cast<uint64_t*>(hraw);
}

// W [K,N] fp32 -> Thi [N,K] fp16 (transpose + round; hi only)
__global__ void transpose_cvt_kernel(const float* __restrict__ W,
                                     __half* __restrict__ Thi,
                                     int K, int N)
{
    __shared__ float tile[32][33];
    int nx = blockIdx.x * 32 + threadIdx.x;
    int k0 = blockIdx.y * 32;
#pragma unroll
    for (int j = 0; j < 32; j += 8)
        tile[threadIdx.y + j][threadIdx.x] = W[(size_t)(k0 + threadIdx.y + j) * N + nx];
    __syncthreads();
    int k = k0 + threadIdx.x;
    int nbase = blockIdx.x * 32 + threadIdx.y;
#pragma unroll
    for (int j = 0; j < 32; j += 8)
        Thi[(size_t)(nbase + j) * K + k] = __float2half_rn(tile[threadIdx.x][threadIdx.y + j]);
}

// ---------------------------------------------------------------------------
// fp16 GEMM via warp mma.sync with cp.async double buffering:
//   C[M,N] = (Ahi [+ Alo])[M,K] @ Bhi[N,K]^T + bias
// Alo == nullptr -> 1-term. CTA 128x128, 8 warps, warp tile 64x32, K-chunk 64.
// ---------------------------------------------------------------------------
#define TBM 128
#define TBN 128
#define TKC 64
#define STRB 144                 // smem row stride bytes (64 fp16 + 16 pad)
#define TILEB (128 * STRB)       // 18432
#define STAGEB (3 * TILEB)       // 55296: [Ahi][Alo][Bhi]
#define GSMEM (2 * STAGEB)       // 110592

__global__ __launch_bounds__(256, 2)
void gemm_mma_kernel(const __half* __restrict__ Ahi,
                     const __half* __restrict__ Alo,
                     const __half* __restrict__ Bhi,
                     const float* __restrict__ bias,
                     float* __restrict__ Cf,
                     __half* __restrict__ Chi,
                     int M, int N, int K)
{
    extern __shared__ char sm[];
    const uint32_t sbase = smem_u32(sm);
    const int tid = threadIdx.x;
    const int wid = tid >> 5;
    const int lane = tid & 31;
    const int m0 = blockIdx.y * TBM;
    const int n0 = blockIdx.x * TBN;
    const int wm = wid & 1;
    const int wn = wid >> 1;

    const int lrowA[4] = { (tid + 0) >> 3, (tid + 256) >> 3,
                           (tid + 512) >> 3, (tid + 768) >> 3 };
    const int lc16 = tid & 7;

    float acc[4][4][4];
#pragma unroll
    for (int i = 0; i < 4; ++i)
#pragma unroll
        for (int j = 0; j < 4; ++j)
#pragma unroll
            for (int k = 0; k < 4; ++k) acc[i][j][k] = 0.f;

    const int arow = lane & 15;
    const int akb  = (lane & 16) ? 16 : 0;
    const int brow = ((lane & 16) ? 8 : 0) + (lane & 7);
    const int bkb  = (lane & 8) ? 16 : 0;

    const uint32_t aHiL = sbase + (wm * 64 + arow) * STRB + akb;
    const uint32_t aLoL = aHiL + TILEB;
    const uint32_t bHiL = sbase + 2 * TILEB + (wn * 32 + brow) * STRB + bkb;

    const int nchunk = K / TKC;

#define GEMM_ISSUE(CHUNK, STAGE)                                              \
    {                                                                         \
        const int k0_ = (CHUNK) * TKC;                                        \
        const uint32_t sb_ = sbase + (STAGE) * STAGEB;                        \
        _Pragma("unroll")                                                     \
        for (int l = 0; l < 4; ++l) {                                         \
            int row = lrowA[l];                                               \
            uint32_t so = row * STRB + lc16 * 16;                             \
            size_t ga = (size_t)(m0 + row) * K + k0_ + lc16 * 8;              \
            size_t gb = (size_t)(n0 + row) * K + k0_ + lc16 * 8;              \
            cp16(sb_ + so, Ahi + ga);                                         \
            if (Alo) cp16(sb_ + TILEB + so, Alo + ga);                        \
            cp16(sb_ + 2 * TILEB + so, Bhi + gb);                             \
        }                                                                     \
    }

    GEMM_ISSUE(0, 0);
    CP_COMMIT();

    for (int c = 0; c < nchunk; ++c) {
        if (c + 1 < nchunk) {
            GEMM_ISSUE(c + 1, (c + 1) & 1);
            CP_COMMIT();
            CP_WAIT1();
        } else {
            CP_WAIT0();
        }
        __syncthreads();

        const uint32_t stoff = (uint32_t)(c & 1) * STAGEB;
#pragma unroll
        for (int ks = 0; ks < 4; ++ks) {
            uint32_t ah[4][4], bh[2][4];
#pragma unroll
            for (int mt = 0; mt < 4; ++mt)
                ldsm4(ah[mt], aHiL + stoff + mt * (16 * STRB) + ks * 32);
#pragma unroll
            for (int np = 0; np < 2; ++np)
                ldsm4(bh[np], bHiL + stoff + np * (16 * STRB) + ks * 32);
#pragma unroll
            for (int mt = 0; mt < 4; ++mt)
#pragma unroll
                for (int nt = 0; nt < 4; ++nt)
                    mma16816f(acc[mt][nt], ah[mt],
                              bh[nt >> 1][(nt & 1) * 2], bh[nt >> 1][(nt & 1) * 2 + 1]);
            if (Alo) {
                uint32_t al[4][4];
#pragma unroll
                for (int mt = 0; mt < 4; ++mt)
                    ldsm4(al[mt], aLoL + stoff + mt * (16 * STRB) + ks * 32);
#pragma unroll
                for (int mt = 0; mt < 4; ++mt)
#pragma unroll
                    for (int nt = 0; nt < 4; ++nt)
                        mma16816f(acc[mt][nt], al[mt],
                                  bh[nt >> 1][(nt & 1) * 2], bh[nt >> 1][(nt & 1) * 2 + 1]);
            }
        }
        __syncthreads();
    }
#undef GEMM_ISSUE

    // Epilogue
    const int rbase = m0 + wm * 64 + (lane >> 2);
    const int cbase = n0 + wn * 32 + (lane & 3) * 2;
    if (Cf) {
#pragma unroll
        for (int mt = 0; mt < 4; ++mt) {
#pragma unroll
            for (int nt = 0; nt < 4; ++nt) {
                int r = rbase + mt * 16;
                int col = cbase + nt * 8;
                float2 bv = *reinterpret_cast<const float2*>(bias + col);
                float2 v0, v1;
                v0.x = acc[mt][nt][0] + bv.x;
                v0.y = acc[mt][nt][1] + bv.y;
                v1.x = acc[mt][nt][2] + bv.x;
                v1.y = acc[mt][nt][3] + bv.y;
                *reinterpret_cast<float2*>(Cf + (size_t)r * N + col) = v0;
                *reinterpret_cast<float2*>(Cf + (size_t)(r + 8) * N + col) = v1;
            }
        }
    } else {
        // hi-only fp16 epilogue
#pragma unroll
        for (int mt = 0; mt < 4; ++mt) {
#pragma unroll
            for (int nt = 0; nt < 4; ++nt) {
                int r = rbase + mt * 16;
                int col = cbase + nt * 8;
                float2 bv = *reinterpret_cast<const float2*>(bias + col);
                uint32_t hp0 = pack_f16x2(acc[mt][nt][0] + bv.x,
                                          acc[mt][nt][1] + bv.y);
                uint32_t hp1 = pack_f16x2(acc[mt][nt][2] + bv.x,
                                          acc[mt][nt][3] + bv.y);
                *reinterpret_cast<uint32_t*>(Chi + (size_t)r * N + col) = hp0;
                *reinterpret_cast<uint32_t*>(Chi + (size_t)(r + 8) * N + col) = hp1;
            }
        }
    }
}

// ---------------------------------------------------------------------------
// Tensor-core flash attention (pure fp16 inputs, fp32 accum), causal,
// muP scale 1/DHEAD, cp.async double-buffered K/V pipeline.
// 128 threads = 4 warps; warp owns 16 query rows. BM=64, BN=64, D=128.
// Reads qkv hi fp16; writes y hi fp16 only.
// ---------------------------------------------------------------------------
#define ASTR 272                 // smem row stride bytes (128 fp16 + 16 pad)
#define ATILE (64 * ASTR)        // 17408 bytes per tile
#define FSM_Q  0
#define FSM_K0 (1 * ATILE)       // K stage 0
#define FSM_K1 (2 * ATILE)       // K stage 1
#define FSM_V0 (3 * ATILE)       // V stage 0
#define FSM_V1 (4 * ATILE)       // V stage 1
#define FSMEM  (5 * ATILE)       // 87040

__global__ __launch_bounds__(128, 2)
void flash_mma_kernel(const __half* __restrict__ qkvh,
                      __half* __restrict__ yh)
{
    extern __shared__ char sm[];
    const uint32_t sbase = smem_u32(sm);
    const int tid = threadIdx.x;
    const int w = tid >> 5;
    const int lane = tid & 31;

    const int qtile = blockIdx.x;
    const int bh = blockIdx.y;
    const int b = bh >> 4;
    const int h = bh & 15;
    const int q0 = qtile * 64;

    // Q load (plain vector loads; covered by in-loop syncs before first read)
#pragma unroll
    for (int l = 0; l < 8; ++l) {
        int f = tid + l * 128;
        int row = f >> 4;
        int c8 = f & 15;
        size_t g = (size_t)(b * SEQ + q0 + row) * QKVDIM + h * DHEAD + c8 * 8;
        uint32_t so = row * ASTR + c8 * 16;
        *reinterpret_cast<uint4*>(sm + FSM_Q + so) =
            *reinterpret_cast<const uint4*>(qkvh + g);
    }

    float o[16][4];
#pragma unroll
    for (int i = 0; i < 16; ++i)
#pragma unroll
        for (int j = 0; j < 4; ++j) o[i][j] = 0.f;
    float mrow[2] = {-CUDART_INF_F, -CUDART_INF_F};
    float lrow[2] = {0.f, 0.f};

    const uint32_t qLane = sbase + FSM_Q + (w * 16 + (lane & 15)) * ASTR +
                           ((lane & 16) ? 16 : 0);
    const uint32_t kLane0 = sbase + FSM_K0 +
                            (((lane & 16) ? 8 : 0) + (lane & 7)) * ASTR +
                            ((lane & 8) ? 16 : 0);
    const uint32_t vLane0 = sbase + FSM_V0 + (lane & 15) * ASTR +
                            ((lane & 16) ? 16 : 0);

    const float SCALE_LOG2E = (1.0f / (float)DHEAD) * 1.44269504088896f;

    // Per-thread KV load geometry: 8 lines per tile (64 rows x 16 x 16B lines)
    const int kvc8 = tid & 15;

#define FLASH_ISSUE(KT, STAGE)                                                \
    {                                                                         \
        const int k0_ = (KT) * 64;                                            \
        const uint32_t koff = sbase + FSM_K0 + (STAGE) * ATILE;               \
        const uint32_t voff = sbase + FSM_V0 + (STAGE) * ATILE;               \
        _Pragma("unroll")                                                     \
        for (int l = 0; l < 8; ++l) {                                         \
            int row = (tid + l * 128) >> 4;                                   \
            size_t g = (size_t)(b * SEQ + k0_ + row) * QKVDIM +               \
                       h * DHEAD + kvc8 * 8;                                  \
            uint32_t so = row * ASTR + kvc8 * 16;                             \
            cp16(koff + so, qkvh + DMODEL + g);                               \
            cp16(voff + so, qkvh + 2 * DMODEL + g);                           \
        }                                                                     \
    }

    FLASH_ISSUE(0, 0);
    CP_COMMIT();

    for (int kt = 0; kt <= qtile; ++kt) {
        __syncthreads();   // all warps done reading the stage we're about to fill
        if (kt + 1 <= qtile) {
            FLASH_ISSUE(kt + 1, (kt + 1) & 1);
            CP_COMMIT();
            CP_WAIT1();
        } else {
            CP_WAIT0();
        }
        __syncthreads();

        const uint32_t stg = (uint32_t)(kt & 1) * ATILE;
        const uint32_t kLane = kLane0 + stg;
        const uint32_t vLane = vLane0 + stg;

        // ---- S = q * k^T ----
        float sacc[8][4];
#pragma unroll
        for (int i = 0; i < 8; ++i)
#pragma unroll
            for (int j = 0; j < 4; ++j) sacc[i][j] = 0.f;

#pragma unroll
        for (int ks = 0; ks < 8; ++ks) {
            uint32_t ah[4];
            ldsm4(ah, qLane + ks * 32);
#pragma unroll
            for (int g = 0; g < 4; ++g) {
                uint32_t bhf[4];
                ldsm4(bhf, kLane + g * (16 * ASTR) + ks * 32);
                mma16816f(sacc[2 * g],     ah, bhf[0], bhf[1]);
                mma16816f(sacc[2 * g + 1], ah, bhf[2], bhf[3]);
            }
        }

        if (kt == qtile) {
            const int rA = w * 16 + (lane >> 2);
#pragma unroll
            for (int nt = 0; nt < 8; ++nt) {
#pragma unroll
                for (int e = 0; e < 4; ++e) {
                    int col = nt * 8 + (lane & 3) * 2 + (e & 1);
                    int row = rA + ((e & 2) ? 8 : 0);
                    if (col > row) sacc[nt][e] = -CUDART_INF_F;
                }
            }
        }

        // ---- online softmax ----
        float mx0 = -CUDART_INF_F, mx1 = -CUDART_INF_F;
#pragma unroll
        for (int nt = 0; nt < 8; ++nt) {
            mx0 = fmaxf(mx0, fmaxf(sacc[nt][0], sacc[nt][1]));
            mx1 = fmaxf(mx1, fmaxf(sacc[nt][2], sacc[nt][3]));
        }
        mx0 = fmaxf(mx0, __shfl_xor_sync(0xffffffffu, mx0, 1));
        mx0 = fmaxf(mx0, __shfl_xor_sync(0xffffffffu, mx0, 2));
        mx1 = fmaxf(mx1, __shfl_xor_sync(0xffffffffu, mx1, 1));
        mx1 = fmaxf(mx1, __shfl_xor_sync(0xffffffffu, mx1, 2));
        float mn0 = fmaxf(mrow[0], mx0 * SCALE_LOG2E);
        float mn1 = fmaxf(mrow[1], mx1 * SCALE_LOG2E);
        float alpha0 = exp2f(mrow[0] - mn0);
        float alpha1 = exp2f(mrow[1] - mn1);
        mrow[0] = mn0; mrow[1] = mn1;

        float sum0 = 0.f, sum1 = 0.f;
#pragma unroll
        for (int nt = 0; nt < 8; ++nt) {
            float p0 = exp2f(sacc[nt][0] * SCALE_LOG2E - mn0);
            float p1 = exp2f(sacc[nt][1] * SCALE_LOG2E - mn0);
            float p2 = exp2f(sacc[nt][2] * SCALE_LOG2E - mn1);
            float p3 = exp2f(sacc[nt][3] * SCALE_LOG2E - mn1);
            sacc[nt][0] = p0; sacc[nt][1] = p1;
            sacc[nt][2] = p2; sacc[nt][3] = p3;
            sum0 += p0 + p1;
            sum1 += p2 + p3;
        }
        sum0 += __shfl_xor_sync(0xffffffffu, sum0, 1);
        sum0 += __shfl_xor_sync(0xffffffffu, sum0, 2);
        sum1 += __shfl_xor_sync(0xffffffffu, sum1, 1);
        sum1 += __shfl_xor_sync(0xffffffffu, sum1, 2);
        lrow[0] = alpha0 * lrow[0] + sum0;
        lrow[1] = alpha1 * lrow[1] + sum1;

#pragma unroll
        for (int nt = 0; nt < 16; ++nt) {
            o[nt][0] *= alpha0; o[nt][1] *= alpha0;
            o[nt][2] *= alpha1; o[nt][3] *= alpha1;
        }

        // ---- O += p * v ----
#pragma unroll
        for (int kc = 0; kc < 4; ++kc) {
            uint32_t pa_h[4];
#pragma unroll
            for (int half = 0; half < 2; ++half) {
                const float* s2 = sacc[2 * kc + half];
#pragma unroll
                for (int rr = 0; rr < 2; ++rr) {
                    pa_h[half * 2 + rr] = pack_f16x2(s2[rr * 2 + 0], s2[rr * 2 + 1]);
                }
            }
#pragma unroll
            for (int ng = 0; ng < 8; ++ng) {
                uint32_t vh[4];
                ldsm4t(vh, vLane + kc * (16 * ASTR) + ng * 32);
                mma16816f(o[2 * ng],     pa_h, vh[0], vh[1]);
                mma16816f(o[2 * ng + 1], pa_h, vh[2], vh[3]);
            }
        }
    }
#undef FLASH_ISSUE

    // ---- epilogue: normalize, write y hi only ----
    const float inv0 = 1.0f / lrow[0];
    const float inv1 = 1.0f / lrow[1];
    const int rowA = q0 + w * 16 + (lane >> 2);
#pragma unroll
    for (int nt = 0; nt < 16; ++nt) {
        int col = h * DHEAD + nt * 8 + (lane & 3) * 2;
        uint32_t hp0 = pack_f16x2(o[nt][0] * inv0, o[nt][1] * inv0);
        uint32_t hp1 = pack_f16x2(o[nt][2] * inv1, o[nt][3] * inv1);
        size_t r0 = (size_t)(b * SEQ + rowA) * DMODEL + col;
        size_t r1 = (size_t)(b * SEQ + rowA + 8) * DMODEL + col;
        *reinterpret_cast<uint32_t*>(yh + r0) = hp0;
        *reinterpret_cast<uint32_t*>(yh + r1) = hp1;
    }
}

// ---------------------------------------------------------------------------
// Launch
// ---------------------------------------------------------------------------
extern "C" void kernel_launch(void* const* d_in, const int* in_sizes, int n_in,
                              void* d_out, int out_size)
{
    const float* x     = (const float*)d_in[0];
    const float* W_qkv = (const float*)d_in[1];
    const float* b_qkv = (const float*)d_in[2];
    const float* W_out = (const float*)d_in[3];
    const float* b_out = (const float*)d_in[4];
    float* out = (float*)d_out;

    void *p_xh, *p_wqh, *p_woh, *p_qh, *p_yh;
    cudaGetSymbolAddress(&p_xh, g_x_hi);
    cudaGetSymbolAddress(&p_wqh, g_wqkv_hi);
    cudaGetSymbolAddress(&p_woh, g_wout_hi);
    cudaGetSymbolAddress(&p_qh, g_qkv_hi);
    cudaGetSymbolAddress(&p_yh, g_y_hi);

    cudaFuncSetAttribute(gemm_mma_kernel,
                         cudaFuncAttributeMaxDynamicSharedMemorySize, GSMEM);
    cudaFuncSetAttribute(flash_mma_kernel,
                         cudaFuncAttributeMaxDynamicSharedMemorySize, FSMEM);

    // 0) Converts
    {
        int n4 = NTOK * DMODEL / 4;
        cvt_kernel<<<(n4 + 255) / 256, 256>>>(x, (__half*)p_xh, n4);
        dim3 blk(32, 8);
        transpose_cvt_kernel<<<dim3(QKVDIM / 32, DMODEL / 32), blk>>>(
            W_qkv, (__half*)p_wqh, DMODEL, QKVDIM);
        transpose_cvt_kernel<<<dim3(DMODEL / 32, DMODEL / 32), blk>>>(
            W_out, (__half*)p_woh, DMODEL, DMODEL);
    }

    // 1) QKV projection (pure fp16, 1-term) -> qkv hi fp16
    gemm_mma_kernel<<<dim3(QKVDIM / TBN, NTOK / TBM), 256, GSMEM>>>(
        (const __half*)p_xh, nullptr, (const __half*)p_wqh,
        b_qkv, nullptr, (__half*)p_qh,
        NTOK, QKVDIM, DMODEL);

    // 2) Attention (pure fp16 flash, cp.async pipelined) -> y hi fp16
    flash_mma_kernel<<<dim3(SEQ / 64, BATCH * NHEADS), 128, FSMEM>>>(
        (const __half*)p_qh, (__half*)p_yh);

    // 3) Output projection (pure fp16, 1-term) -> fp32 out
    gemm_mma_kernel<<<dim3(DMODEL / TBN, NTOK / TBM), 256, GSMEM>>>(
        (const __half*)p_yh, nullptr, (const __half*)p_woh,
        b_out, out, nullptr,
        NTOK, DMODEL, DMODEL);
}